// round 9
// baseline (speedup 1.0000x reference)
#include <cuda_runtime.h>
#include <cuda_fp16.h>
#include <cstdint>

#define NTOK    65536
#define VOCAB   50257
#define VOCABP  50304                 // 786 * 64
#define NVT64   (VOCABP / 64)         // 786 tiles
#define THREADS 256

// ---------------- scratch (device globals: allocation-free) ----------------
__device__ __half g_Hv[(size_t)VOCABP * 512];    // compacted activations (in-place)
__device__ float  g_R[(size_t)VOCABP * 512];     // compacted final table
__device__ __half g_W0h[2048 * 512];
__device__ __half g_W1h[2048 * 512];
__device__ __half g_Wlh[512 * 512];
__device__ int    g_used[VOCABP];
__device__ int    g_slot[VOCABP];
__device__ int    g_uid[VOCABP];
__device__ int    g_nuniq;

// ---------------- helpers ----------------
__device__ __forceinline__ uint32_t smem_u32(const void* p) {
    uint32_t a;
    asm("{ .reg .u64 t; cvta.to.shared.u64 t, %1; cvt.u32.u64 %0, t; }"
        : "=r"(a) : "l"(p));
    return a;
}
__device__ __forceinline__ void cp16(uint32_t dst, const void* src) {
    asm volatile("cp.async.cg.shared.global [%0], [%1], 16;"
                 :: "r"(dst), "l"(src));
}
__device__ __forceinline__ uint4 ldsm_x4(uint32_t a) {
    uint4 v;
    asm volatile("ldmatrix.sync.aligned.m8n8.x4.shared.b16 {%0,%1,%2,%3}, [%4];"
                 : "=r"(v.x), "=r"(v.y), "=r"(v.z), "=r"(v.w) : "r"(a));
    return v;
}
__device__ __forceinline__ void mma_f16(float c[4], const uint4& a,
                                        uint32_t b0, uint32_t b1) {
    asm volatile(
        "mma.sync.aligned.m16n8k16.row.col.f32.f16.f16.f32 "
        "{%0,%1,%2,%3}, {%4,%5,%6,%7}, {%8,%9}, {%0,%1,%2,%3};"
        : "+f"(c[0]), "+f"(c[1]), "+f"(c[2]), "+f"(c[3])
        : "r"(a.x), "r"(a.y), "r"(a.z), "r"(a.w), "r"(b0), "r"(b1));
}
// sig(x)*tanh(y) = (1 - e^{-2y}) / ((1 + e^{-x}) (1 + e^{-2y}))
__device__ __forceinline__ float sigtanh(float x, float y) {
    float ex = __expf(-x);
    float ey = __expf(-2.0f * y);
    return __fdividef(1.0f - ey, (1.0f + ex) * (1.0f + ey));
}

// ---------------- dedup pipeline ----------------
__global__ void __launch_bounds__(256) reset_k() {
    int i = blockIdx.x * 256 + threadIdx.x;
    if (i < VOCABP) g_used[i] = 0;
    if (i == 0) g_nuniq = 0;
}
__global__ void __launch_bounds__(256) mark_k(const int* __restrict__ ids) {
    int t = blockIdx.x * 256 + threadIdx.x;
    if (t < NTOK) g_used[ids[t]] = 1;
}
__global__ void __launch_bounds__(256) compact_k() {
    int i = blockIdx.x * 256 + threadIdx.x;
    int used = (i < VOCABP) ? g_used[i] : 0;
    unsigned bal = __ballot_sync(0xffffffffu, used);
    int lane = threadIdx.x & 31, warp = threadIdx.x >> 5;
    __shared__ int wbase[8];
    __shared__ int bbase;
    if (lane == 0) wbase[warp] = __popc(bal);
    __syncthreads();
    if (threadIdx.x == 0) {
        int s = 0;
        #pragma unroll
        for (int w = 0; w < 8; ++w) { int c = wbase[w]; wbase[w] = s; s += c; }
        bbase = atomicAdd(&g_nuniq, s);
    }
    __syncthreads();
    if (used) {
        int rank = bbase + wbase[warp] + __popc(bal & ((1u << lane) - 1));
        g_slot[i] = rank;
        g_uid[rank] = i;
    }
}

// ---------------- prep: all f32 weights -> f16, one launch ----------------
__global__ void __launch_bounds__(256) f2h_all(const float* __restrict__ W0,
                                               const float* __restrict__ W1,
                                               const float* __restrict__ Wl) {
    int i = blockIdx.x * 256 + threadIdx.x;
    if (i >= 589824) return;
    const float* src; __half* dst; int off;
    if (i < 262144)      { src = W0; dst = g_W0h; off = i; }
    else if (i < 524288) { src = W1; dst = g_W1h; off = i - 262144; }
    else                 { src = Wl; dst = g_Wlh; off = i - 524288; }
    float4 v = ((const float4*)src)[off];
    __half2 a = __floats2half2_rn(v.x, v.y);
    __half2 b = __floats2half2_rn(v.z, v.w);
    uint2 u;
    u.x = *(uint32_t*)&a; u.y = *(uint32_t*)&b;
    *(uint2*)(dst + (size_t)off * 4) = u;
}

// ---------------- compacted emb gather -> f16 table (zero tail rows) ----------------
__global__ void __launch_bounds__(256) emb_gather(const float* __restrict__ emb) {
    size_t i = (size_t)blockIdx.x * 256 + threadIdx.x;   // VOCABP*64 threads
    int row = (int)(i >> 6);
    int c = (int)(i & 63) * 8;
    uint4 u = make_uint4(0, 0, 0, 0);
    if (row < g_nuniq) {
        int id = g_uid[row];
        const float4* p = (const float4*)(emb + (size_t)id * 512 + c);
        float4 v0 = p[0], v1 = p[1];
        __half2 h0 = __floats2half2_rn(v0.x, v0.y);
        __half2 h1 = __floats2half2_rn(v0.z, v0.w);
        __half2 h2 = __floats2half2_rn(v1.x, v1.y);
        __half2 h3 = __floats2half2_rn(v1.z, v1.w);
        u.x = *(uint32_t*)&h0; u.y = *(uint32_t*)&h1;
        u.z = *(uint32_t*)&h2; u.w = *(uint32_t*)&h3;
    }
    *(uint4*)(g_Hv + i * 8) = u;
}

// ======= fused layer0 -> layer1 -> final, 64-row tile, 2 CTAs/SM =======
// smem: A resident 64 x 1040B; B 3 stages x 192 x 80B; bias f16 (layers) / f32 (fin)
#define LA_STRIDE 1040
#define L_AOFF    0
#define L_BOFF    (64 * LA_STRIDE)             // 66560
#define L_BSTAGE  (192 * 80)                   // 15360
#define F_BSTAGE  (128 * 80)                   // 10240
#define L_BIASOFF (L_BOFF + 3 * L_BSTAGE)      // 112640
#define L_SMEM    (L_BIASOFF + 3072)           // 115712  (x2 = 231424 <= SM limit)

__global__ void __launch_bounds__(THREADS, 2) fused_gemm(
    const float* __restrict__ bih0, const float* __restrict__ bhh0,
    const float* __restrict__ bih1, const float* __restrict__ bhh1,
    const float* __restrict__ blin)
{
    const int tok0 = blockIdx.x * 64;
    if (tok0 >= g_nuniq) return;

    extern __shared__ char smem[];
    const int tid  = threadIdx.x;
    const int lane = tid & 31, wid = tid >> 5;
    const int mw = wid >> 1, nw = wid & 1;      // 4 M-warps x 2 N-warps
    const uint32_t sb = smem_u32(smem);
    __half* bias_h = (__half*)(smem + L_BIASOFF);
    float*  bias_f = (float*)(smem + L_BIASOFF);

    __half* Arows = g_Hv + (size_t)tok0 * 512;

    const int within = lane & 7, grp = lane >> 3;
    // A (non-trans): warp tile 16m; single 16x16 tile pair per ks
    const uint32_t aBase = sb + L_AOFF +
        (uint32_t)(mw * 16 + within + 8 * (grp & 1)) * LA_STRIDE + (grp >> 1) * 16;
    // layer B: per gate, units nw*32..+31 -> 2 ldsm (t=0,1) per ks
    uint32_t bL[3];
    #pragma unroll
    for (int g = 0; g < 3; ++g) {
        int n = g * 64 + nw * 32 + within + 8 * (grp >> 1);
        bL[g] = (uint32_t)n * 80 + (grp & 1) * 16;
    }
    // fin B: 64 out-cols per warp -> 4 ldsm (t=0..3) per ks
    uint32_t bF[4];
    #pragma unroll
    for (int t = 0; t < 4; ++t) {
        int n = nw * 64 + t * 16 + within + 8 * (grp >> 1);
        bF[t] = (uint32_t)n * 80 + (grp & 1) * 16;
    }

    // A resident load: 4096 x 16B, 16 per thread
    auto loadA = [&]() {
        #pragma unroll
        for (int j = 0; j < 16; ++j) {
            int idx = tid + 256 * j;
            int r = idx >> 6, c16 = idx & 63;
            cp16(sb + L_AOFF + (uint32_t)r * LA_STRIDE + c16 * 16,
                 Arows + (size_t)r * 512 + c16 * 8);
        }
    };

    // ================= LSTM phases =================
    for (int L = 0; L < 2; ++L) {
        const __half* Wh   = L ? g_W1h : g_W0h;
        const float*  b_ih = L ? bih1 : bih0;
        const float*  b_hh = L ? bhh1 : bhh0;

        if (L) { __threadfence_block(); }
        __syncthreads();

        for (int j = tid; j < 512; j += THREADS) {
            bias_h[j]        = __float2half(b_ih[j]        + b_hh[j]);          // i
            bias_h[512 + j]  = __float2half(b_ih[1024 + j] + b_hh[1024 + j]);   // g
            bias_h[1024 + j] = __float2half(b_ih[1536 + j] + b_hh[1536 + j]);   // o
        }

        auto stage_copyB = [&](int stage, int ncc, int kc) {
            const uint32_t b_s = sb + L_BOFF + stage * L_BSTAGE;
            #pragma unroll
            for (int j = 0; j < 3; ++j) {
                int idx = tid + 256 * j;
                int n = idx >> 2, c8 = idx & 3;
                int gate = n >> 6, nn = n & 63;
                int grow = (gate + (gate > 0)) * 512 + ncc * 64 + nn; // skip f
                cp16(b_s + (uint32_t)n * 80 + c8 * 16,
                     Wh + (size_t)grow * 512 + kc * 32 + c8 * 8);
            }
            asm volatile("cp.async.commit_group;" ::: "memory");
        };

        loadA();
        stage_copyB(0, 0, 0);
        stage_copyB(1, 0, 1);

        float acc[3][4][4];     // gate, n8-frag, frag

        for (int nc = 0; nc < 8; ++nc) {
            #pragma unroll
            for (int g = 0; g < 3; ++g)
                #pragma unroll
                for (int f = 0; f < 4; ++f)
                    #pragma unroll
                    for (int q = 0; q < 4; ++q) acc[g][f][q] = 0.0f;

            for (int kc = 0; kc < 16; ++kc) {
                if (kc < 15) asm volatile("cp.async.wait_group 1;" ::: "memory");
                else         asm volatile("cp.async.wait_group 0;" ::: "memory");
                __syncthreads();

                const uint32_t b_s = sb + L_BOFF + (kc % 3) * L_BSTAGE;

                uint4 af[2];
                #pragma unroll
                for (int ks = 0; ks < 2; ++ks)
                    af[ks] = ldsm_x4(aBase + (kc * 32 + ks * 16) * 2);

                #pragma unroll
                for (int g = 0; g < 3; ++g) {
                    #pragma unroll
                    for (int ks = 0; ks < 2; ++ks) {
                        #pragma unroll
                        for (int t = 0; t < 2; ++t) {
                            uint4 bv = ldsm_x4(b_s + bL[g] + t * (16 * 80) + ks * 32);
                            mma_f16(acc[g][2 * t + 0], af[ks], bv.x, bv.y);
                            mma_f16(acc[g][2 * t + 1], af[ks], bv.z, bv.w);
                        }
                    }
                }
                if (kc < 14) stage_copyB((kc + 2) % 3, nc, kc + 2);
            }
            __syncthreads();
            if (nc < 7) { stage_copyB(0, nc + 1, 0); stage_copyB(1, nc + 1, 1); }

            // epilogue: h = sig(o)*tanh( sig(i)*tanh(g) )
            #pragma unroll
            for (int f = 0; f < 4; ++f) {
                const int u = nc * 64 + nw * 32 + f * 8 + 2 * (lane & 3);
                const float bi0 = __half2float(bias_h[u]);
                const float bi1 = __half2float(bias_h[u + 1]);
                const float bg0 = __half2float(bias_h[512 + u]);
                const float bg1 = __half2float(bias_h[512 + u + 1]);
                const float bo0 = __half2float(bias_h[1024 + u]);
                const float bo1 = __half2float(bias_h[1024 + u + 1]);
                #pragma unroll
                for (int e = 0; e < 2; ++e) {
                    const int row = mw * 16 + e * 8 + (lane >> 2);
                    float c0 = sigtanh(acc[0][f][2 * e + 0] + bi0,
                                       acc[1][f][2 * e + 0] + bg0);
                    float c1 = sigtanh(acc[0][f][2 * e + 1] + bi1,
                                       acc[1][f][2 * e + 1] + bg1);
                    float h0 = sigtanh(acc[2][f][2 * e + 0] + bo0, c0);
                    float h1 = sigtanh(acc[2][f][2 * e + 1] + bo1, c1);
                    *(__half2*)(Arows + (size_t)row * 512 + u) =
                        __floats2half2_rn(h0, h1);
                }
            }
        }
    }

    // ================= final linear phase =================
    __threadfence_block();
    __syncthreads();
    for (int j = tid; j < 512; j += THREADS) bias_f[j] = blin[j];

    auto stage_copyF = [&](int stage, int ncc, int kc) {
        const uint32_t b_s = sb + L_BOFF + stage * F_BSTAGE;
        #pragma unroll
        for (int j = 0; j < 2; ++j) {
            int idx = tid + 256 * j;
            int n = idx >> 2, c8 = idx & 3;
            int grow = ncc * 128 + n;
            cp16(b_s + (uint32_t)n * 80 + c8 * 16,
                 g_Wlh + (size_t)grow * 512 + kc * 32 + c8 * 8);
        }
        asm volatile("cp.async.commit_group;" ::: "memory");
    };

    loadA();
    stage_copyF(0, 0, 0);
    stage_copyF(1, 0, 1);

    float facc[8][4];

    for (int nc = 0; nc < 4; ++nc) {
        #pragma unroll
        for (int f = 0; f < 8; ++f)
            #pragma unroll
            for (int q = 0; q < 4; ++q) facc[f][q] = 0.0f;

        for (int kc = 0; kc < 16; ++kc) {
            if (kc < 15) asm volatile("cp.async.wait_group 1;" ::: "memory");
            else         asm volatile("cp.async.wait_group 0;" ::: "memory");
            __syncthreads();

            const uint32_t b_s = sb + L_BOFF + (kc % 3) * F_BSTAGE;

            uint4 af[2];
            #pragma unroll
            for (int ks = 0; ks < 2; ++ks)
                af[ks] = ldsm_x4(aBase + (kc * 32 + ks * 16) * 2);

            #pragma unroll
            for (int ks = 0; ks < 2; ++ks) {
                #pragma unroll
                for (int t = 0; t < 4; ++t) {
                    uint4 bv = ldsm_x4(b_s + bF[t] + ks * 32);
                    mma_f16(facc[2 * t + 0], af[ks], bv.x, bv.y);
                    mma_f16(facc[2 * t + 1], af[ks], bv.z, bv.w);
                }
            }
            if (kc < 14) stage_copyF((kc + 2) % 3, nc, kc + 2);
        }
        __syncthreads();
        if (nc < 3) { stage_copyF(0, nc + 1, 0); stage_copyF(1, nc + 1, 1); }

        #pragma unroll
        for (int f = 0; f < 8; ++f) {
            const int col = nc * 128 + nw * 64 + f * 8 + 2 * (lane & 3);
            const float b0 = bias_f[col], b1 = bias_f[col + 1];
            #pragma unroll
            for (int e = 0; e < 2; ++e) {
                const int row = mw * 16 + e * 8 + (lane >> 2);
                float v0 = fmaxf(facc[f][2 * e + 0] + b0, 0.0f);
                float v1 = fmaxf(facc[f][2 * e + 1] + b1, 0.0f);
                *(float2*)(g_R + (size_t)(tok0 + row) * 512 + col) =
                    make_float2(v0, v1);
            }
        }
    }
}

// ---------------- scatter: out[t,:] = R[slot[ids[t]],:] ----------------
__global__ void __launch_bounds__(256) scatter_out(const int* __restrict__ ids,
                                                   float* __restrict__ out) {
    size_t i = (size_t)blockIdx.x * 256 + threadIdx.x;   // NTOK*128 threads
    int token = (int)(i >> 7);
    int c4 = (int)(i & 127);
    int slot = g_slot[ids[token]];
    float4 v = *(const float4*)(g_R + (size_t)slot * 512 + c4 * 4);
    ((float4*)out)[i] = v;
}

// ---------------- launch ----------------
extern "C" void kernel_launch(void* const* d_in, const int* in_sizes, int n_in,
                              void* d_out, int out_size) {
    (void)in_sizes; (void)n_in; (void)out_size;
    const int*   ids  = (const int*)d_in[0];
    const float* emb  = (const float*)d_in[1];
    const float* Wih0 = (const float*)d_in[2];
    const float* bih0 = (const float*)d_in[4];
    const float* bhh0 = (const float*)d_in[5];
    const float* Wih1 = (const float*)d_in[6];
    const float* bih1 = (const float*)d_in[8];
    const float* bhh1 = (const float*)d_in[9];
    const float* Wlin = (const float*)d_in[10];
    const float* blin = (const float*)d_in[11];
    float* out = (float*)d_out;

    cudaFuncSetAttribute(fused_gemm,
                         cudaFuncAttributeMaxDynamicSharedMemorySize, L_SMEM);

    reset_k<<<(VOCABP + 255) / 256, 256>>>();
    mark_k<<<NTOK / 256, 256>>>(ids);
    compact_k<<<(VOCABP + 255) / 256, 256>>>();
    f2h_all<<<(589824 + 255) / 256, 256>>>(Wih0, Wih1, Wlin);
    emb_gather<<<(VOCABP * 64) / 256, 256>>>(emb);
    fused_gemm<<<NVT64, THREADS, L_SMEM>>>(bih0, bhh0, bih1, bhh1, blin);
    scatter_out<<<(NTOK * 128) / 256, 256>>>(ids, out);
}

// round 10
// speedup vs baseline: 1.0318x; 1.0318x over previous
#include <cuda_runtime.h>
#include <cuda_fp16.h>
#include <cstdint>

#define NTOK    65536
#define VOCAB   50257
#define VOCABP  50304                 // 393 * 128
#define NVT     (VOCABP / 128)        // 393 tiles
#define THREADS 256

// ---------------- scratch (device globals: allocation-free) ----------------
__device__ __half g_Hv [(size_t)VOCABP * 512];   // emb table / layer1 output
__device__ __half g_Hv2[(size_t)VOCABP * 512];   // layer0 output
__device__ float  g_R[(size_t)VOCABP * 512];     // final table
__device__ __half g_W0h[2048 * 512];
__device__ __half g_W1h[2048 * 512];
__device__ __half g_Wlh[512 * 512];
__device__ int    g_used[VOCABP];
__device__ int    g_slot[VOCABP];
__device__ int    g_uid[VOCABP];
__device__ int    g_nuniq;

// ---------------- helpers ----------------
__device__ __forceinline__ uint32_t smem_u32(const void* p) {
    uint32_t a;
    asm("{ .reg .u64 t; cvta.to.shared.u64 t, %1; cvt.u32.u64 %0, t; }"
        : "=r"(a) : "l"(p));
    return a;
}
__device__ __forceinline__ void cp16(uint32_t dst, const void* src) {
    asm volatile("cp.async.cg.shared.global [%0], [%1], 16;"
                 :: "r"(dst), "l"(src));
}
__device__ __forceinline__ uint4 ldsm_x4(uint32_t a) {
    uint4 v;
    asm volatile("ldmatrix.sync.aligned.m8n8.x4.shared.b16 {%0,%1,%2,%3}, [%4];"
                 : "=r"(v.x), "=r"(v.y), "=r"(v.z), "=r"(v.w) : "r"(a));
    return v;
}
__device__ __forceinline__ void mma_f16(float c[4], const uint4& a,
                                        uint32_t b0, uint32_t b1) {
    asm volatile(
        "mma.sync.aligned.m16n8k16.row.col.f32.f16.f16.f32 "
        "{%0,%1,%2,%3}, {%4,%5,%6,%7}, {%8,%9}, {%0,%1,%2,%3};"
        : "+f"(c[0]), "+f"(c[1]), "+f"(c[2]), "+f"(c[3])
        : "r"(a.x), "r"(a.y), "r"(a.z), "r"(a.w), "r"(b0), "r"(b1));
}
// sig(x)*tanh(y) = (1 - e^{-2y}) / ((1 + e^{-x}) (1 + e^{-2y}))
__device__ __forceinline__ float sigtanh(float x, float y) {
    float ex = __expf(-x);
    float ey = __expf(-2.0f * y);
    return __fdividef(1.0f - ey, (1.0f + ex) * (1.0f + ey));
}

// ---------------- dedup pipeline ----------------
__global__ void __launch_bounds__(256) reset_k() {
    int i = blockIdx.x * 256 + threadIdx.x;
    if (i < VOCABP) g_used[i] = 0;
    if (i == 0) g_nuniq = 0;
}
__global__ void __launch_bounds__(256) mark_k(const int* __restrict__ ids) {
    int t = blockIdx.x * 256 + threadIdx.x;
    if (t < NTOK) g_used[ids[t]] = 1;
}
__global__ void __launch_bounds__(256) compact_k() {
    int i = blockIdx.x * 256 + threadIdx.x;
    int used = (i < VOCABP) ? g_used[i] : 0;
    unsigned bal = __ballot_sync(0xffffffffu, used);
    int lane = threadIdx.x & 31, warp = threadIdx.x >> 5;
    __shared__ int wbase[8];
    __shared__ int bbase;
    if (lane == 0) wbase[warp] = __popc(bal);
    __syncthreads();
    if (threadIdx.x == 0) {
        int s = 0;
        #pragma unroll
        for (int w = 0; w < 8; ++w) { int c = wbase[w]; wbase[w] = s; s += c; }
        bbase = atomicAdd(&g_nuniq, s);
    }
    __syncthreads();
    if (used) {
        int rank = bbase + wbase[warp] + __popc(bal & ((1u << lane) - 1));
        g_slot[i] = rank;
        g_uid[rank] = i;
    }
}

// ---------------- prep: all f32 weights -> f16, one launch ----------------
__global__ void __launch_bounds__(256) f2h_all(const float* __restrict__ W0,
                                               const float* __restrict__ W1,
                                               const float* __restrict__ Wl) {
    int i = blockIdx.x * 256 + threadIdx.x;
    if (i >= 589824) return;
    const float* src; __half* dst; int off;
    if (i < 262144)      { src = W0; dst = g_W0h; off = i; }
    else if (i < 524288) { src = W1; dst = g_W1h; off = i - 262144; }
    else                 { src = Wl; dst = g_Wlh; off = i - 524288; }
    float4 v = ((const float4*)src)[off];
    __half2 a = __floats2half2_rn(v.x, v.y);
    __half2 b = __floats2half2_rn(v.z, v.w);
    uint2 u;
    u.x = *(uint32_t*)&a; u.y = *(uint32_t*)&b;
    *(uint2*)(dst + (size_t)off * 4) = u;
}

// ---------------- compacted emb gather -> f16 table (zero tail rows) ----------------
__global__ void __launch_bounds__(256) emb_gather(const float* __restrict__ emb) {
    size_t i = (size_t)blockIdx.x * 256 + threadIdx.x;   // VOCABP*64 threads
    int row = (int)(i >> 6);
    int c = (int)(i & 63) * 8;
    uint4 u = make_uint4(0, 0, 0, 0);
    if (row < g_nuniq) {
        int id = g_uid[row];
        const float4* p = (const float4*)(emb + (size_t)id * 512 + c);
        float4 v0 = p[0], v1 = p[1];
        __half2 h0 = __floats2half2_rn(v0.x, v0.y);
        __half2 h1 = __floats2half2_rn(v0.z, v0.w);
        __half2 h2 = __floats2half2_rn(v1.x, v1.y);
        __half2 h3 = __floats2half2_rn(v1.z, v1.w);
        u.x = *(uint32_t*)&h0; u.y = *(uint32_t*)&h1;
        u.z = *(uint32_t*)&h2; u.w = *(uint32_t*)&h3;
    }
    *(uint4*)(g_Hv + i * 8) = u;
}

// ======= fused layer0 -> layer1 -> final, 128-row tile, streamed A, 2 CTAs/SM =======
// smem ring: 3 stages x [A 128x80B | B up to 128x80B]; f32 bias 3x512
#define A_ST     10240
#define STAGE    20480
#define BIASOFF  (3 * STAGE)          // 61440
#define SMEM_TOT (BIASOFF + 6144)     // 67584  (x2 CTAs = 135168)

__global__ void __launch_bounds__(THREADS, 2) fused_gemm(
    const float* __restrict__ bih0, const float* __restrict__ bhh0,
    const float* __restrict__ bih1, const float* __restrict__ bhh1,
    const float* __restrict__ blin)
{
    const int tok0 = blockIdx.x * 128;
    if (tok0 >= g_nuniq) return;

    extern __shared__ char smem[];
    const int tid  = threadIdx.x;
    const int lane = tid & 31, wid = tid >> 5;
    const int mw = wid >> 1, nw = wid & 1;      // 4 M-warps x 2 N-warps
    const uint32_t sb = smem_u32(smem);
    float* bias_s = (float*)(smem + BIASOFF);

    const int within = lane & 7, grp = lane >> 3;
    // A (staged, 80B rows): warp tile 32m; mi2 x ks2 ldsm.x4
    uint32_t aOff[2];
    #pragma unroll
    for (int mi = 0; mi < 2; ++mi)
        aOff[mi] = (uint32_t)(mw * 32 + mi * 16 + within + 8 * (grp & 1)) * 80
                 + (grp >> 1) * 16;
    // layer B: per gate 16n per warp -> 1 ldsm.x4 per ks
    uint32_t bOffL[3];
    #pragma unroll
    for (int g = 0; g < 3; ++g)
        bOffL[g] = (uint32_t)(g * 32 + nw * 16 + within + 8 * (grp >> 1)) * 80
                 + (grp & 1) * 16;
    // fin B: 64n per warp -> 4 ldsm.x4 per ks
    uint32_t bOffF[4];
    #pragma unroll
    for (int t = 0; t < 4; ++t)
        bOffF[t] = (uint32_t)(nw * 64 + t * 16 + within + 8 * (grp >> 1)) * 80
                 + (grp & 1) * 16;

    // ================= LSTM phases =================
    for (int L = 0; L < 2; ++L) {
        const __half* Xr = (L ? g_Hv2 : g_Hv) + (size_t)tok0 * 512;
        __half*       Yr = (L ? g_Hv  : g_Hv2) + (size_t)tok0 * 512;
        const __half* Wh   = L ? g_W1h : g_W0h;
        const float*  b_ih = L ? bih1 : bih0;
        const float*  b_hh = L ? bhh1 : bhh0;

        if (L) __threadfence_block();           // h STGs -> visible to cp.async
        __syncthreads();

        for (int j = tid; j < 512; j += THREADS) {
            bias_s[j]        = b_ih[j]        + b_hh[j];          // i
            bias_s[512 + j]  = b_ih[1024 + j] + b_hh[1024 + j];   // g
            bias_s[1024 + j] = b_ih[1536 + j] + b_hh[1536 + j];   // o
        }

        // stage load: A chunk (512 cp16) + B 96 rows (384 cp16)
        auto loadL = [&](int it) {
            const int ncc = it >> 4, kc = it & 15;
            const uint32_t s = sb + (it % 3) * STAGE;
            #pragma unroll
            for (int j = 0; j < 4; ++j) {
                int t = tid + 256 * j;
                if (t < 512) {
                    int r = t >> 2, c = t & 3;
                    cp16(s + (uint32_t)r * 80 + c * 16,
                         Xr + (size_t)r * 512 + kc * 32 + c * 8);
                } else if (t < 896) {
                    int u = t - 512;
                    int n = u >> 2, c = u & 3;
                    int gate = n >> 5, nn = n & 31;
                    int grow = (gate + (gate > 0)) * 512 + ncc * 32 + nn; // skip f
                    cp16(s + A_ST + (uint32_t)n * 80 + c * 16,
                         Wh + (size_t)grow * 512 + kc * 32 + c * 8);
                }
            }
            asm volatile("cp.async.commit_group;" ::: "memory");
        };

        loadL(0); loadL(1);

        for (int nc = 0; nc < 16; ++nc) {
            float acc[3][2][2][4];
            #pragma unroll
            for (int g = 0; g < 3; ++g)
                #pragma unroll
                for (int mi = 0; mi < 2; ++mi)
                    #pragma unroll
                    for (int ni = 0; ni < 2; ++ni)
                        #pragma unroll
                        for (int q = 0; q < 4; ++q) acc[g][mi][ni][q] = 0.0f;

            for (int kc = 0; kc < 16; ++kc) {
                const int it = nc * 16 + kc;
                if (it < 255) asm volatile("cp.async.wait_group 1;" ::: "memory");
                else          asm volatile("cp.async.wait_group 0;" ::: "memory");
                __syncthreads();

                const uint32_t st = sb + (it % 3) * STAGE;

                uint4 af[2][2];
                #pragma unroll
                for (int mi = 0; mi < 2; ++mi)
                    #pragma unroll
                    for (int ks = 0; ks < 2; ++ks)
                        af[mi][ks] = ldsm_x4(st + aOff[mi] + ks * 32);

                #pragma unroll
                for (int g = 0; g < 3; ++g) {
                    #pragma unroll
                    for (int ks = 0; ks < 2; ++ks) {
                        uint4 bv = ldsm_x4(st + A_ST + bOffL[g] + ks * 32);
                        #pragma unroll
                        for (int mi = 0; mi < 2; ++mi) {
                            mma_f16(acc[g][mi][0], af[mi][ks], bv.x, bv.y);
                            mma_f16(acc[g][mi][1], af[mi][ks], bv.z, bv.w);
                        }
                    }
                }
                if (it + 2 < 256) loadL(it + 2);
            }

            // epilogue: h = sig(o)*tanh( sig(i)*tanh(g) )
            #pragma unroll
            for (int mi = 0; mi < 2; ++mi) {
                #pragma unroll
                for (int ni = 0; ni < 2; ++ni) {
                    const int col = nc * 32 + nw * 16 + ni * 8 + 2 * (lane & 3);
                    const float bi0 = bias_s[col],        bi1 = bias_s[col + 1];
                    const float bg0 = bias_s[512 + col],  bg1 = bias_s[512 + col + 1];
                    const float bo0 = bias_s[1024 + col], bo1 = bias_s[1024 + col + 1];
                    #pragma unroll
                    for (int e = 0; e < 2; ++e) {
                        const int row = mw * 32 + mi * 16 + e * 8 + (lane >> 2);
                        float c0 = sigtanh(acc[0][mi][ni][2 * e + 0] + bi0,
                                           acc[1][mi][ni][2 * e + 0] + bg0);
                        float c1 = sigtanh(acc[0][mi][ni][2 * e + 1] + bi1,
                                           acc[1][mi][ni][2 * e + 1] + bg1);
                        float h0 = sigtanh(acc[2][mi][ni][2 * e + 0] + bo0, c0);
                        float h1 = sigtanh(acc[2][mi][ni][2 * e + 1] + bo1, c1);
                        *(__half2*)(Yr + (size_t)row * 512 + col) =
                            __floats2half2_rn(h0, h1);
                    }
                }
            }
        }
    }

    // ================= final linear phase =================
    {
        const __half* Xr = g_Hv + (size_t)tok0 * 512;
        __threadfence_block();
        __syncthreads();
        for (int j = tid; j < 512; j += THREADS) bias_s[j] = blin[j];

        auto loadF = [&](int it) {
            const int ncc = it >> 4, kc = it & 15;
            const uint32_t s = sb + (it % 3) * STAGE;
            #pragma unroll
            for (int j = 0; j < 4; ++j) {
                int t = tid + 256 * j;
                if (t < 512) {
                    int r = t >> 2, c = t & 3;
                    cp16(s + (uint32_t)r * 80 + c * 16,
                         Xr + (size_t)r * 512 + kc * 32 + c * 8);
                } else {
                    int u = t - 512;
                    int n = u >> 2, c = u & 3;
                    int grow = ncc * 128 + n;
                    cp16(s + A_ST + (uint32_t)n * 80 + c * 16,
                         g_Wlh + (size_t)grow * 512 + kc * 32 + c * 8);
                }
            }
            asm volatile("cp.async.commit_group;" ::: "memory");
        };

        loadF(0); loadF(1);

        for (int nc = 0; nc < 4; ++nc) {
            float facc[2][8][4];
            #pragma unroll
            for (int mi = 0; mi < 2; ++mi)
                #pragma unroll
                for (int ni = 0; ni < 8; ++ni)
                    #pragma unroll
                    for (int q = 0; q < 4; ++q) facc[mi][ni][q] = 0.0f;

            for (int kc = 0; kc < 16; ++kc) {
                const int it = nc * 16 + kc;
                if (it < 63) asm volatile("cp.async.wait_group 1;" ::: "memory");
                else         asm volatile("cp.async.wait_group 0;" ::: "memory");
                __syncthreads();

                const uint32_t st = sb + (it % 3) * STAGE;

                uint4 af[2][2];
                #pragma unroll
                for (int mi = 0; mi < 2; ++mi)
                    #pragma unroll
                    for (int ks = 0; ks < 2; ++ks)
                        af[mi][ks] = ldsm_x4(st + aOff[mi] + ks * 32);

                #pragma unroll
                for (int ks = 0; ks < 2; ++ks) {
                    #pragma unroll
                    for (int t = 0; t < 4; ++t) {
                        uint4 bv = ldsm_x4(st + A_ST + bOffF[t] + ks * 32);
                        #pragma unroll
                        for (int mi = 0; mi < 2; ++mi) {
                            mma_f16(facc[mi][2 * t + 0], af[mi][ks], bv.x, bv.y);
                            mma_f16(facc[mi][2 * t + 1], af[mi][ks], bv.z, bv.w);
                        }
                    }
                }
                if (it + 2 < 64) loadF(it + 2);
            }

            #pragma unroll
            for (int mi = 0; mi < 2; ++mi) {
                #pragma unroll
                for (int ni = 0; ni < 8; ++ni) {
                    const int col = nc * 128 + nw * 64 + ni * 8 + 2 * (lane & 3);
                    const float b0 = bias_s[col], b1 = bias_s[col + 1];
                    #pragma unroll
                    for (int e = 0; e < 2; ++e) {
                        const int row = mw * 32 + mi * 16 + e * 8 + (lane >> 2);
                        float v0 = fmaxf(facc[mi][ni][2 * e + 0] + b0, 0.0f);
                        float v1 = fmaxf(facc[mi][ni][2 * e + 1] + b1, 0.0f);
                        *(float2*)(g_R + (size_t)(tok0 + row) * 512 + col) =
                            make_float2(v0, v1);
                    }
                }
            }
        }
    }
}

// ---------------- scatter: out[t,:] = R[slot[ids[t]],:] ----------------
__global__ void __launch_bounds__(256) scatter_out(const int* __restrict__ ids,
                                                   float* __restrict__ out) {
    size_t i = (size_t)blockIdx.x * 256 + threadIdx.x;   // NTOK*128 threads
    int token = (int)(i >> 7);
    int c4 = (int)(i & 127);
    int slot = g_slot[ids[token]];
    float4 v = *(const float4*)(g_R + (size_t)slot * 512 + c4 * 4);
    ((float4*)out)[i] = v;
}

// ---------------- launch ----------------
extern "C" void kernel_launch(void* const* d_in, const int* in_sizes, int n_in,
                              void* d_out, int out_size) {
    (void)in_sizes; (void)n_in; (void)out_size;
    const int*   ids  = (const int*)d_in[0];
    const float* emb  = (const float*)d_in[1];
    const float* Wih0 = (const float*)d_in[2];
    const float* bih0 = (const float*)d_in[4];
    const float* bhh0 = (const float*)d_in[5];
    const float* Wih1 = (const float*)d_in[6];
    const float* bih1 = (const float*)d_in[8];
    const float* bhh1 = (const float*)d_in[9];
    const float* Wlin = (const float*)d_in[10];
    const float* blin = (const float*)d_in[11];
    float* out = (float*)d_out;

    cudaFuncSetAttribute(fused_gemm,
                         cudaFuncAttributeMaxDynamicSharedMemorySize, SMEM_TOT);

    reset_k<<<(VOCABP + 255) / 256, 256>>>();
    mark_k<<<NTOK / 256, 256>>>(ids);
    compact_k<<<(VOCABP + 255) / 256, 256>>>();
    f2h_all<<<(589824 + 255) / 256, 256>>>(Wih0, Wih1, Wlin);
    emb_gather<<<(VOCABP * 64) / 256, 256>>>(emb);
    fused_gemm<<<NVT, THREADS, SMEM_TOT>>>(bih0, bhh0, bih1, bhh1, blin);
    scatter_out<<<(NTOK * 128) / 256, 256>>>(ids, out);
}

// round 11
// speedup vs baseline: 1.1109x; 1.0766x over previous
#include <cuda_runtime.h>
#include <cuda_fp16.h>
#include <cstdint>

#define NTOK    65536
#define VOCAB   50257
#define VOCABP  50304                 // 393 * 128
#define NVT     (VOCABP / 128)        // 393 tiles
#define THREADS 256

// ---------------- scratch (device globals: allocation-free) ----------------
__device__ __half g_Hv[(size_t)VOCABP * 512];    // activations (in-place per phase)
__device__ float  g_R[(size_t)VOCABP * 512];     // final table
__device__ __half g_W0h[2048 * 512];
__device__ __half g_W1h[2048 * 512];
__device__ __half g_Wlh[512 * 512];
__device__ int    g_used[VOCABP];
__device__ int    g_slot[VOCABP];
__device__ int    g_uid[VOCABP];
__device__ int    g_nuniq;

// ---------------- helpers ----------------
__device__ __forceinline__ uint32_t smem_u32(const void* p) {
    uint32_t a;
    asm("{ .reg .u64 t; cvta.to.shared.u64 t, %1; cvt.u32.u64 %0, t; }"
        : "=r"(a) : "l"(p));
    return a;
}
__device__ __forceinline__ void cp16(uint32_t dst, const void* src) {
    asm volatile("cp.async.cg.shared.global [%0], [%1], 16;"
                 :: "r"(dst), "l"(src));
}
__device__ __forceinline__ uint4 ldsm_x4(uint32_t a) {
    uint4 v;
    asm volatile("ldmatrix.sync.aligned.m8n8.x4.shared.b16 {%0,%1,%2,%3}, [%4];"
                 : "=r"(v.x), "=r"(v.y), "=r"(v.z), "=r"(v.w) : "r"(a));
    return v;
}
__device__ __forceinline__ void mma_f16(float c[4], const uint4& a,
                                        uint32_t b0, uint32_t b1) {
    asm volatile(
        "mma.sync.aligned.m16n8k16.row.col.f32.f16.f16.f32 "
        "{%0,%1,%2,%3}, {%4,%5,%6,%7}, {%8,%9}, {%0,%1,%2,%3};"
        : "+f"(c[0]), "+f"(c[1]), "+f"(c[2]), "+f"(c[3])
        : "r"(a.x), "r"(a.y), "r"(a.z), "r"(a.w), "r"(b0), "r"(b1));
}
// sig(x)*tanh(y) = (1 - e^{-2y}) / ((1 + e^{-x}) (1 + e^{-2y}))
__device__ __forceinline__ float sigtanh(float x, float y) {
    float ex = __expf(-x);
    float ey = __expf(-2.0f * y);
    return __fdividef(1.0f - ey, (1.0f + ex) * (1.0f + ey));
}

// ---------------- dedup pipeline ----------------
__global__ void __launch_bounds__(256) reset_k() {
    int i = blockIdx.x * 256 + threadIdx.x;
    if (i < VOCABP) g_used[i] = 0;
    if (i == 0) g_nuniq = 0;
}
__global__ void __launch_bounds__(256) mark_k(const int* __restrict__ ids) {
    int t = blockIdx.x * 256 + threadIdx.x;
    if (t < NTOK) g_used[ids[t]] = 1;
}
__global__ void __launch_bounds__(256) compact_k() {
    int i = blockIdx.x * 256 + threadIdx.x;
    int used = (i < VOCABP) ? g_used[i] : 0;
    unsigned bal = __ballot_sync(0xffffffffu, used);
    int lane = threadIdx.x & 31, warp = threadIdx.x >> 5;
    __shared__ int wbase[8];
    __shared__ int bbase;
    if (lane == 0) wbase[warp] = __popc(bal);
    __syncthreads();
    if (threadIdx.x == 0) {
        int s = 0;
        #pragma unroll
        for (int w = 0; w < 8; ++w) { int c = wbase[w]; wbase[w] = s; s += c; }
        bbase = atomicAdd(&g_nuniq, s);
    }
    __syncthreads();
    if (used) {
        int rank = bbase + wbase[warp] + __popc(bal & ((1u << lane) - 1));
        g_slot[i] = rank;
        g_uid[rank] = i;
    }
}

// ---------------- prep: all f32 weights -> f16, one launch ----------------
__global__ void __launch_bounds__(256) f2h_all(const float* __restrict__ W0,
                                               const float* __restrict__ W1,
                                               const float* __restrict__ Wl) {
    int i = blockIdx.x * 256 + threadIdx.x;
    if (i >= 589824) return;
    const float* src; __half* dst; int off;
    if (i < 262144)      { src = W0; dst = g_W0h; off = i; }
    else if (i < 524288) { src = W1; dst = g_W1h; off = i - 262144; }
    else                 { src = Wl; dst = g_Wlh; off = i - 524288; }
    float4 v = ((const float4*)src)[off];
    __half2 a = __floats2half2_rn(v.x, v.y);
    __half2 b = __floats2half2_rn(v.z, v.w);
    uint2 u;
    u.x = *(uint32_t*)&a; u.y = *(uint32_t*)&b;
    *(uint2*)(dst + (size_t)off * 4) = u;
}

// ---------------- compacted emb gather -> f16 table (zero tail rows) ----------------
__global__ void __launch_bounds__(256) emb_gather(const float* __restrict__ emb) {
    size_t i = (size_t)blockIdx.x * 256 + threadIdx.x;   // VOCABP*64 threads
    int row = (int)(i >> 6);
    int c = (int)(i & 63) * 8;
    uint4 u = make_uint4(0, 0, 0, 0);
    if (row < g_nuniq) {
        int id = g_uid[row];
        const float4* p = (const float4*)(emb + (size_t)id * 512 + c);
        float4 v0 = p[0], v1 = p[1];
        __half2 h0 = __floats2half2_rn(v0.x, v0.y);
        __half2 h1 = __floats2half2_rn(v0.z, v0.w);
        __half2 h2 = __floats2half2_rn(v1.x, v1.y);
        __half2 h3 = __floats2half2_rn(v1.z, v1.w);
        u.x = *(uint32_t*)&h0; u.y = *(uint32_t*)&h1;
        u.z = *(uint32_t*)&h2; u.w = *(uint32_t*)&h3;
    }
    *(uint4*)(g_Hv + i * 8) = u;
}

// ======= fused layer0 -> layer1 -> final, 128-row tile, resident A, K-chunk 64 =======
// smem: A resident 128 x 1040B; B 3 stages x 192 x 144B; bias 3x512 f32
#define LA_STRIDE 1040
#define L_AOFF    0
#define L_BOFF    (128 * LA_STRIDE)            // 133120
#define BST       (192 * 144)                  // 27648
#define L_BIASOFF (L_BOFF + 3 * BST)           // 216064
#define L_SMEM    (L_BIASOFF + 6144)           // 222208

__global__ void __launch_bounds__(THREADS, 1) fused_gemm(
    const float* __restrict__ bih0, const float* __restrict__ bhh0,
    const float* __restrict__ bih1, const float* __restrict__ bhh1,
    const float* __restrict__ blin)
{
    const int tok0 = blockIdx.x * 128;
    if (tok0 >= g_nuniq) return;

    extern __shared__ char smem[];
    const int tid  = threadIdx.x;
    const int lane = tid & 31, wid = tid >> 5;
    const int mw = wid >> 2, nw = wid & 3;      // 2 M-warps x 4 N-warps
    const uint32_t sb = smem_u32(smem);
    float* bias_s = (float*)(smem + L_BIASOFF);

    __half* Arows = g_Hv + (size_t)tok0 * 512;

    const int within = lane & 7, grp = lane >> 3;
    uint32_t aBase[4];
    #pragma unroll
    for (int mi = 0; mi < 4; ++mi) {
        int m = mw * 64 + mi * 16 + within + 8 * (grp & 1);
        aBase[mi] = sb + L_AOFF + (uint32_t)m * LA_STRIDE + (grp >> 1) * 16;
    }
    uint32_t bOffL[3];                          // layer: per gate 16n per warp
    #pragma unroll
    for (int g = 0; g < 3; ++g) {
        int n = g * 64 + nw * 16 + within + 8 * (grp >> 1);
        bOffL[g] = (uint32_t)n * 144 + (grp & 1) * 16;
    }
    uint32_t bOffF[2];                          // fin: 32n per warp
    #pragma unroll
    for (int t = 0; t < 2; ++t) {
        int n = nw * 32 + t * 16 + within + 8 * (grp >> 1);
        bOffF[t] = (uint32_t)n * 144 + (grp & 1) * 16;
    }

    auto loadA = [&]() {
        #pragma unroll
        for (int j = 0; j < 32; ++j) {
            int idx = tid + 256 * j;
            int r = idx >> 6, c16 = idx & 63;
            cp16(sb + L_AOFF + (uint32_t)r * LA_STRIDE + c16 * 16,
                 Arows + (size_t)r * 512 + c16 * 8);
        }
    };

    // ================= LSTM phases =================
    for (int L = 0; L < 2; ++L) {
        const __half* Wh   = L ? g_W1h : g_W0h;
        const float*  b_ih = L ? bih1 : bih0;
        const float*  b_hh = L ? bhh1 : bhh0;

        if (L) __threadfence_block();
        __syncthreads();

        for (int j = tid; j < 512; j += THREADS) {
            bias_s[j]        = b_ih[j]        + b_hh[j];          // i
            bias_s[512 + j]  = b_ih[1024 + j] + b_hh[1024 + j];   // g
            bias_s[1024 + j] = b_ih[1536 + j] + b_hh[1536 + j];   // o
        }

        // stage load: B 192 rows x 64 halfs (128B) -> 1536 cp16, 6/thread
        auto stage_copyB = [&](int it) {
            const int ncc = it >> 3, kc = it & 7;
            const uint32_t b_s = sb + L_BOFF + (it % 3) * BST;
            #pragma unroll
            for (int j = 0; j < 6; ++j) {
                int idx = tid + 256 * j;
                int n = idx >> 3, c8 = idx & 7;
                int gate = n >> 6, nn = n & 63;
                int grow = (gate + (gate > 0)) * 512 + ncc * 64 + nn; // skip f
                cp16(b_s + (uint32_t)n * 144 + c8 * 16,
                     Wh + (size_t)grow * 512 + kc * 64 + c8 * 8);
            }
            asm volatile("cp.async.commit_group;" ::: "memory");
        };

        loadA();
        stage_copyB(0);          // group 0 = A + B stage0
        stage_copyB(1);

        for (int nc = 0; nc < 8; ++nc) {
            float acc[3][4][2][4];
            #pragma unroll
            for (int g = 0; g < 3; ++g)
                #pragma unroll
                for (int mi = 0; mi < 4; ++mi)
                    #pragma unroll
                    for (int ni = 0; ni < 2; ++ni)
                        #pragma unroll
                        for (int q = 0; q < 4; ++q) acc[g][mi][ni][q] = 0.0f;

            for (int kc = 0; kc < 8; ++kc) {
                const int it = nc * 8 + kc;
                if (it < 63) asm volatile("cp.async.wait_group 1;" ::: "memory");
                else         asm volatile("cp.async.wait_group 0;" ::: "memory");
                __syncthreads();

                const uint32_t b_s = sb + L_BOFF + (it % 3) * BST;

                #pragma unroll
                for (int ks = 0; ks < 4; ++ks) {
                    uint4 af[4];
                    #pragma unroll
                    for (int mi = 0; mi < 4; ++mi)
                        af[mi] = ldsm_x4(aBase[mi] + (kc * 64 + ks * 16) * 2);
                    #pragma unroll
                    for (int g = 0; g < 3; ++g) {
                        uint4 bv = ldsm_x4(b_s + bOffL[g] + ks * 32);
                        #pragma unroll
                        for (int mi = 0; mi < 4; ++mi) {
                            mma_f16(acc[g][mi][0], af[mi], bv.x, bv.y);
                            mma_f16(acc[g][mi][1], af[mi], bv.z, bv.w);
                        }
                    }
                }
                if (it + 2 < 64) stage_copyB(it + 2);
            }

            // epilogue: h = sig(o)*tanh( sig(i)*tanh(g) )
            #pragma unroll
            for (int mi = 0; mi < 4; ++mi) {
                #pragma unroll
                for (int ni = 0; ni < 2; ++ni) {
                    const int col = nc * 64 + nw * 16 + ni * 8 + 2 * (lane & 3);
                    const float bi0 = bias_s[col],        bi1 = bias_s[col + 1];
                    const float bg0 = bias_s[512 + col],  bg1 = bias_s[512 + col + 1];
                    const float bo0 = bias_s[1024 + col], bo1 = bias_s[1024 + col + 1];
                    #pragma unroll
                    for (int e = 0; e < 2; ++e) {
                        const int row = mw * 64 + mi * 16 + e * 8 + (lane >> 2);
                        float c0 = sigtanh(acc[0][mi][ni][2 * e + 0] + bi0,
                                           acc[1][mi][ni][2 * e + 0] + bg0);
                        float c1 = sigtanh(acc[0][mi][ni][2 * e + 1] + bi1,
                                           acc[1][mi][ni][2 * e + 1] + bg1);
                        float h0 = sigtanh(acc[2][mi][ni][2 * e + 0] + bo0, c0);
                        float h1 = sigtanh(acc[2][mi][ni][2 * e + 1] + bo1, c1);
                        *(__half2*)(Arows + (size_t)row * 512 + col) =
                            __floats2half2_rn(h0, h1);
                    }
                }
            }
        }
    }

    // ================= final linear phase =================
    __threadfence_block();
    __syncthreads();
    for (int j = tid; j < 512; j += THREADS) bias_s[j] = blin[j];

    auto stage_copyF = [&](int it) {
        const int ncc = it >> 3, kc = it & 7;
        const uint32_t b_s = sb + L_BOFF + (it % 3) * BST;
        #pragma unroll
        for (int j = 0; j < 4; ++j) {
            int idx = tid + 256 * j;
            int n = idx >> 3, c8 = idx & 7;
            int grow = ncc * 128 + n;
            cp16(b_s + (uint32_t)n * 144 + c8 * 16,
                 g_Wlh + (size_t)grow * 512 + kc * 64 + c8 * 8);
        }
        asm volatile("cp.async.commit_group;" ::: "memory");
    };

    loadA();
    stage_copyF(0);
    stage_copyF(1);

    for (int nc = 0; nc < 4; ++nc) {
        float facc[4][4][4];
        #pragma unroll
        for (int mi = 0; mi < 4; ++mi)
            #pragma unroll
            for (int ni = 0; ni < 4; ++ni)
                #pragma unroll
                for (int q = 0; q < 4; ++q) facc[mi][ni][q] = 0.0f;

        for (int kc = 0; kc < 8; ++kc) {
            const int it = nc * 8 + kc;
            if (it < 31) asm volatile("cp.async.wait_group 1;" ::: "memory");
            else         asm volatile("cp.async.wait_group 0;" ::: "memory");
            __syncthreads();

            const uint32_t b_s = sb + L_BOFF + (it % 3) * BST;

            #pragma unroll
            for (int ks = 0; ks < 4; ++ks) {
                uint4 af[4];
                #pragma unroll
                for (int mi = 0; mi < 4; ++mi)
                    af[mi] = ldsm_x4(aBase[mi] + (kc * 64 + ks * 16) * 2);
                #pragma unroll
                for (int t = 0; t < 2; ++t) {
                    uint4 bv = ldsm_x4(b_s + bOffF[t] + ks * 32);
                    #pragma unroll
                    for (int mi = 0; mi < 4; ++mi) {
                        mma_f16(facc[mi][2 * t + 0], af[mi], bv.x, bv.y);
                        mma_f16(facc[mi][2 * t + 1], af[mi], bv.z, bv.w);
                    }
                }
            }
            if (it + 2 < 32) stage_copyF(it + 2);
        }

        #pragma unroll
        for (int mi = 0; mi < 4; ++mi) {
            #pragma unroll
            for (int ni = 0; ni < 4; ++ni) {
                const int col = nc * 128 + nw * 32 + ni * 8 + 2 * (lane & 3);
                const float b0 = bias_s[col], b1 = bias_s[col + 1];
                #pragma unroll
                for (int e = 0; e < 2; ++e) {
                    const int row = mw * 64 + mi * 16 + e * 8 + (lane >> 2);
                    float v0 = fmaxf(facc[mi][ni][2 * e + 0] + b0, 0.0f);
                    float v1 = fmaxf(facc[mi][ni][2 * e + 1] + b1, 0.0f);
                    *(float2*)(g_R + (size_t)(tok0 + row) * 512 + col) =
                        make_float2(v0, v1);
                }
            }
        }
    }
}

// ---------------- scatter: out[t,:] = R[slot[ids[t]],:] ----------------
__global__ void __launch_bounds__(256) scatter_out(const int* __restrict__ ids,
                                                   float* __restrict__ out) {
    size_t i = (size_t)blockIdx.x * 256 + threadIdx.x;   // NTOK*128 threads
    int token = (int)(i >> 7);
    int c4 = (int)(i & 127);
    int slot = g_slot[ids[token]];
    float4 v = *(const float4*)(g_R + (size_t)slot * 512 + c4 * 4);
    __stcs(((float4*)out) + i, v);   // streaming store: don't pollute L2
}

// ---------------- launch ----------------
extern "C" void kernel_launch(void* const* d_in, const int* in_sizes, int n_in,
                              void* d_out, int out_size) {
    (void)in_sizes; (void)n_in; (void)out_size;
    const int*   ids  = (const int*)d_in[0];
    const float* emb  = (const float*)d_in[1];
    const float* Wih0 = (const float*)d_in[2];
    const float* bih0 = (const float*)d_in[4];
    const float* bhh0 = (const float*)d_in[5];
    const float* Wih1 = (const float*)d_in[6];
    const float* bih1 = (const float*)d_in[8];
    const float* bhh1 = (const float*)d_in[9];
    const float* Wlin = (const float*)d_in[10];
    const float* blin = (const float*)d_in[11];
    float* out = (float*)d_out;

    cudaFuncSetAttribute(fused_gemm,
                         cudaFuncAttributeMaxDynamicSharedMemorySize, L_SMEM);

    reset_k<<<(VOCABP + 255) / 256, 256>>>();
    mark_k<<<NTOK / 256, 256>>>(ids);
    compact_k<<<(VOCABP + 255) / 256, 256>>>();
    f2h_all<<<(589824 + 255) / 256, 256>>>(Wih0, Wih1, Wlin);
    emb_gather<<<(VOCABP * 64) / 256, 256>>>(emb);
    fused_gemm<<<NVT, THREADS, L_SMEM>>>(bih0, bhh0, bih1, bhh1, blin);
    scatter_out<<<(NTOK * 128) / 256, 256>>>(ids, out);
}

// round 12
// speedup vs baseline: 1.1378x; 1.0242x over previous
#include <cuda_runtime.h>
#include <cuda_fp16.h>
#include <cstdint>

#define NTOK    65536
#define VOCAB   50257
#define VOCABP  50304                 // 393 * 128
#define NVT     (VOCABP / 128)        // 393 tiles
#define THREADS 256

// ---------------- scratch (device globals: allocation-free) ----------------
__device__ __half g_Hv[(size_t)VOCABP * 512];    // activations (in-place per phase)
__device__ float  g_R[(size_t)VOCABP * 512];     // final table
__device__ __half g_W0h[2048 * 512];
__device__ __half g_W1h[2048 * 512];
__device__ __half g_Wlh[512 * 512];
__device__ int    g_used[VOCABP];
__device__ int    g_slot[VOCABP];
__device__ int    g_uid[VOCABP];
__device__ int    g_nuniq;

// ---------------- helpers ----------------
__device__ __forceinline__ uint32_t smem_u32(const void* p) {
    uint32_t a;
    asm("{ .reg .u64 t; cvta.to.shared.u64 t, %1; cvt.u32.u64 %0, t; }"
        : "=r"(a) : "l"(p));
    return a;
}
__device__ __forceinline__ void cp16(uint32_t dst, const void* src) {
    asm volatile("cp.async.cg.shared.global [%0], [%1], 16;"
                 :: "r"(dst), "l"(src));
}
__device__ __forceinline__ uint4 ldsm_x4(uint32_t a) {
    uint4 v;
    asm volatile("ldmatrix.sync.aligned.m8n8.x4.shared.b16 {%0,%1,%2,%3}, [%4];"
                 : "=r"(v.x), "=r"(v.y), "=r"(v.z), "=r"(v.w) : "r"(a));
    return v;
}
__device__ __forceinline__ void mma_f16(float c[4], const uint4& a,
                                        uint32_t b0, uint32_t b1) {
    asm volatile(
        "mma.sync.aligned.m16n8k16.row.col.f32.f16.f16.f32 "
        "{%0,%1,%2,%3}, {%4,%5,%6,%7}, {%8,%9}, {%0,%1,%2,%3};"
        : "+f"(c[0]), "+f"(c[1]), "+f"(c[2]), "+f"(c[3])
        : "r"(a.x), "r"(a.y), "r"(a.z), "r"(a.w), "r"(b0), "r"(b1));
}
// sig(x)*tanh(y) = (1 - e^{-2y}) / ((1 + e^{-x}) (1 + e^{-2y}))
__device__ __forceinline__ float sigtanh(float x, float y) {
    float ex = __expf(-x);
    float ey = __expf(-2.0f * y);
    return __fdividef(1.0f - ey, (1.0f + ex) * (1.0f + ey));
}

// ---------------- dedup pipeline ----------------
__global__ void __launch_bounds__(256) reset_k() {
    int i = blockIdx.x * 256 + threadIdx.x;
    if (i < VOCABP) g_used[i] = 0;
    if (i == 0) g_nuniq = 0;
}
__global__ void __launch_bounds__(256) mark_k(const int* __restrict__ ids) {
    int t = blockIdx.x * 256 + threadIdx.x;
    if (t < NTOK) g_used[ids[t]] = 1;
}
__global__ void __launch_bounds__(256) compact_k() {
    int i = blockIdx.x * 256 + threadIdx.x;
    int used = (i < VOCABP) ? g_used[i] : 0;
    unsigned bal = __ballot_sync(0xffffffffu, used);
    int lane = threadIdx.x & 31, warp = threadIdx.x >> 5;
    __shared__ int wbase[8];
    __shared__ int bbase;
    if (lane == 0) wbase[warp] = __popc(bal);
    __syncthreads();
    if (threadIdx.x == 0) {
        int s = 0;
        #pragma unroll
        for (int w = 0; w < 8; ++w) { int c = wbase[w]; wbase[w] = s; s += c; }
        bbase = atomicAdd(&g_nuniq, s);
    }
    __syncthreads();
    if (used) {
        int rank = bbase + wbase[warp] + __popc(bal & ((1u << lane) - 1));
        g_slot[i] = rank;
        g_uid[rank] = i;
    }
}

// ---------------- prep: all f32 weights -> f16, one launch ----------------
__global__ void __launch_bounds__(256) f2h_all(const float* __restrict__ W0,
                                               const float* __restrict__ W1,
                                               const float* __restrict__ Wl) {
    int i = blockIdx.x * 256 + threadIdx.x;
    if (i >= 589824) return;
    const float* src; __half* dst; int off;
    if (i < 262144)      { src = W0; dst = g_W0h; off = i; }
    else if (i < 524288) { src = W1; dst = g_W1h; off = i - 262144; }
    else                 { src = Wl; dst = g_Wlh; off = i - 524288; }
    float4 v = ((const float4*)src)[off];
    __half2 a = __floats2half2_rn(v.x, v.y);
    __half2 b = __floats2half2_rn(v.z, v.w);
    uint2 u;
    u.x = *(uint32_t*)&a; u.y = *(uint32_t*)&b;
    *(uint2*)(dst + (size_t)off * 4) = u;
}

// ---------------- compacted emb gather -> f16 table (zero tail rows) ----------------
__global__ void __launch_bounds__(256) emb_gather(const float* __restrict__ emb) {
    size_t i = (size_t)blockIdx.x * 256 + threadIdx.x;   // VOCABP*64 threads
    int row = (int)(i >> 6);
    int c = (int)(i & 63) * 8;
    uint4 u = make_uint4(0, 0, 0, 0);
    if (row < g_nuniq) {
        int id = g_uid[row];
        const float4* p = (const float4*)(emb + (size_t)id * 512 + c);
        float4 v0 = p[0], v1 = p[1];
        __half2 h0 = __floats2half2_rn(v0.x, v0.y);
        __half2 h1 = __floats2half2_rn(v0.z, v0.w);
        __half2 h2 = __floats2half2_rn(v1.x, v1.y);
        __half2 h3 = __floats2half2_rn(v1.z, v1.w);
        u.x = *(uint32_t*)&h0; u.y = *(uint32_t*)&h1;
        u.z = *(uint32_t*)&h2; u.w = *(uint32_t*)&h3;
    }
    *(uint4*)(g_Hv + i * 8) = u;
}

// === fused layer0 -> layer1 -> final, 128-row tile, resident A, paired barriers ===
// smem: A resident 128 x 1040B; B 4 stages x 192 x 80B; bias 3x512 f32
#define LA_STRIDE 1040
#define L_AOFF    0
#define L_BOFF    (128 * LA_STRIDE)            // 133120
#define L_BSTAGE  (192 * 80)                   // 15360
#define F_BSTAGE  (128 * 80)                   // 10240
#define L_BIASOFF (L_BOFF + 4 * L_BSTAGE)      // 194560
#define L_SMEM    (L_BIASOFF + 6144)           // 200704

__global__ void __launch_bounds__(THREADS, 1) fused_gemm(
    const float* __restrict__ bih0, const float* __restrict__ bhh0,
    const float* __restrict__ bih1, const float* __restrict__ bhh1,
    const float* __restrict__ blin)
{
    const int tok0 = blockIdx.x * 128;
    if (tok0 >= g_nuniq) return;

    extern __shared__ char smem[];
    const int tid  = threadIdx.x;
    const int lane = tid & 31, wid = tid >> 5;
    const int mw = wid >> 2, nw = wid & 3;      // 2 M-warps x 4 N-warps
    const uint32_t sb = smem_u32(smem);
    float* bias_s = (float*)(smem + L_BIASOFF);

    __half* Arows = g_Hv + (size_t)tok0 * 512;

    const int within = lane & 7, grp = lane >> 3;
    uint32_t aBase[4];
    #pragma unroll
    for (int mi = 0; mi < 4; ++mi) {
        int m = mw * 64 + mi * 16 + within + 8 * (grp & 1);
        aBase[mi] = sb + L_AOFF + (uint32_t)m * LA_STRIDE + (grp >> 1) * 16;
    }
    uint32_t bOffL[3];                          // layer: per gate 16n per warp
    #pragma unroll
    for (int g = 0; g < 3; ++g) {
        int n = g * 64 + nw * 16 + within + 8 * (grp >> 1);
        bOffL[g] = (uint32_t)n * 80 + (grp & 1) * 16;
    }
    uint32_t bOffF[2];                          // fin: 32n per warp
    #pragma unroll
    for (int t = 0; t < 2; ++t) {
        int n = nw * 32 + t * 16 + within + 8 * (grp >> 1);
        bOffF[t] = (uint32_t)n * 80 + (grp & 1) * 16;
    }

    auto loadA = [&]() {
        #pragma unroll
        for (int j = 0; j < 32; ++j) {
            int idx = tid + 256 * j;
            int r = idx >> 6, c16 = idx & 63;
            cp16(sb + L_AOFF + (uint32_t)r * LA_STRIDE + c16 * 16,
                 Arows + (size_t)r * 512 + c16 * 8);
        }
    };

    // ================= LSTM phases =================
    for (int L = 0; L < 2; ++L) {
        const __half* Wh   = L ? g_W1h : g_W0h;
        const float*  b_ih = L ? bih1 : bih0;
        const float*  b_hh = L ? bhh1 : bhh0;

        if (L) __threadfence_block();
        __syncthreads();

        for (int j = tid; j < 512; j += THREADS) {
            bias_s[j]        = b_ih[j]        + b_hh[j];          // i
            bias_s[512 + j]  = b_ih[1024 + j] + b_hh[1024 + j];   // g
            bias_s[1024 + j] = b_ih[1536 + j] + b_hh[1536 + j];   // o
        }

        // copy ONE stage (it = global kc index 0..127); no commit
        auto copy1L = [&](int it) {
            const int ncc = it >> 4, kc = it & 15;
            const uint32_t b_s = sb + L_BOFF + (it & 3) * L_BSTAGE;
            #pragma unroll
            for (int j = 0; j < 3; ++j) {
                int idx = tid + 256 * j;
                int n = idx >> 2, c8 = idx & 3;
                int gate = n >> 6, nn = n & 63;
                int grow = (gate + (gate > 0)) * 512 + ncc * 64 + nn; // skip f
                cp16(b_s + (uint32_t)n * 80 + c8 * 16,
                     Wh + (size_t)grow * 512 + kc * 32 + c8 * 8);
            }
        };
        #define COMMIT() asm volatile("cp.async.commit_group;" ::: "memory")

        loadA();
        copy1L(0); copy1L(1); COMMIT();        // group: A + pair(0,1)
        copy1L(2); copy1L(3); COMMIT();        // group: pair(2,3)

        for (int nc = 0; nc < 8; ++nc) {
            float acc[3][4][2][4];
            #pragma unroll
            for (int g = 0; g < 3; ++g)
                #pragma unroll
                for (int mi = 0; mi < 4; ++mi)
                    #pragma unroll
                    for (int ni = 0; ni < 2; ++ni)
                        #pragma unroll
                        for (int q = 0; q < 4; ++q) acc[g][mi][ni][q] = 0.0f;

            for (int pj = 0; pj < 8; ++pj) {           // 8 pairs per nc
                const int jglob = nc * 8 + pj;         // 0..63
                if (jglob < 63) asm volatile("cp.async.wait_group 1;" ::: "memory");
                else            asm volatile("cp.async.wait_group 0;" ::: "memory");
                __syncthreads();

                #pragma unroll 1
                for (int k = 0; k < 2; ++k) {
                    const int it = jglob * 2 + k;
                    const int kc = it & 15;
                    const uint32_t b_s = sb + L_BOFF + (it & 3) * L_BSTAGE;

                    uint4 af[4][2];
                    #pragma unroll
                    for (int mi = 0; mi < 4; ++mi)
                        #pragma unroll
                        for (int ks = 0; ks < 2; ++ks)
                            af[mi][ks] = ldsm_x4(aBase[mi] + (kc * 32 + ks * 16) * 2);

                    #pragma unroll
                    for (int g = 0; g < 3; ++g) {
                        #pragma unroll
                        for (int ks = 0; ks < 2; ++ks) {
                            uint4 bv = ldsm_x4(b_s + bOffL[g] + ks * 32);
                            #pragma unroll
                            for (int mi = 0; mi < 4; ++mi) {
                                mma_f16(acc[g][mi][0], af[mi][ks], bv.x, bv.y);
                                mma_f16(acc[g][mi][1], af[mi][ks], bv.z, bv.w);
                            }
                        }
                    }
                }
                if (jglob <= 61) {                      // refill pair jglob+2
                    copy1L(jglob * 2 + 4);
                    copy1L(jglob * 2 + 5);
                    COMMIT();
                }
            }

            // epilogue: h = sig(o)*tanh( sig(i)*tanh(g) )
            #pragma unroll
            for (int mi = 0; mi < 4; ++mi) {
                #pragma unroll
                for (int ni = 0; ni < 2; ++ni) {
                    const int col = nc * 64 + nw * 16 + ni * 8 + 2 * (lane & 3);
                    const float bi0 = bias_s[col],        bi1 = bias_s[col + 1];
                    const float bg0 = bias_s[512 + col],  bg1 = bias_s[512 + col + 1];
                    const float bo0 = bias_s[1024 + col], bo1 = bias_s[1024 + col + 1];
                    #pragma unroll
                    for (int e = 0; e < 2; ++e) {
                        const int row = mw * 64 + mi * 16 + e * 8 + (lane >> 2);
                        float c0 = sigtanh(acc[0][mi][ni][2 * e + 0] + bi0,
                                           acc[1][mi][ni][2 * e + 0] + bg0);
                        float c1 = sigtanh(acc[0][mi][ni][2 * e + 1] + bi1,
                                           acc[1][mi][ni][2 * e + 1] + bg1);
                        float h0 = sigtanh(acc[2][mi][ni][2 * e + 0] + bo0, c0);
                        float h1 = sigtanh(acc[2][mi][ni][2 * e + 1] + bo1, c1);
                        *(__half2*)(Arows + (size_t)row * 512 + col) =
                            __floats2half2_rn(h0, h1);
                    }
                }
            }
        }
    }

    // ================= final linear phase =================
    __threadfence_block();
    __syncthreads();
    for (int j = tid; j < 512; j += THREADS) bias_s[j] = blin[j];

    auto copy1F = [&](int it) {
        const int ncc = it >> 4, kc = it & 15;
        const uint32_t b_s = sb + L_BOFF + (it & 3) * F_BSTAGE;
        #pragma unroll
        for (int j = 0; j < 2; ++j) {
            int idx = tid + 256 * j;
            int n = idx >> 2, c8 = idx & 3;
            int grow = ncc * 128 + n;
            cp16(b_s + (uint32_t)n * 80 + c8 * 16,
                 g_Wlh + (size_t)grow * 512 + kc * 32 + c8 * 8);
        }
    };

    loadA();
    copy1F(0); copy1F(1); COMMIT();
    copy1F(2); copy1F(3); COMMIT();

    for (int nc = 0; nc < 4; ++nc) {
        float facc[4][4][4];
        #pragma unroll
        for (int mi = 0; mi < 4; ++mi)
            #pragma unroll
            for (int ni = 0; ni < 4; ++ni)
                #pragma unroll
                for (int q = 0; q < 4; ++q) facc[mi][ni][q] = 0.0f;

        for (int pj = 0; pj < 8; ++pj) {
            const int jglob = nc * 8 + pj;             // 0..31
            if (jglob < 31) asm volatile("cp.async.wait_group 1;" ::: "memory");
            else            asm volatile("cp.async.wait_group 0;" ::: "memory");
            __syncthreads();

            #pragma unroll 1
            for (int k = 0; k < 2; ++k) {
                const int it = jglob * 2 + k;
                const int kc = it & 15;
                const uint32_t b_s = sb + L_BOFF + (it & 3) * F_BSTAGE;

                uint4 af[4][2];
                #pragma unroll
                for (int mi = 0; mi < 4; ++mi)
                    #pragma unroll
                    for (int ks = 0; ks < 2; ++ks)
                        af[mi][ks] = ldsm_x4(aBase[mi] + (kc * 32 + ks * 16) * 2);

                #pragma unroll
                for (int t = 0; t < 2; ++t) {
                    #pragma unroll
                    for (int ks = 0; ks < 2; ++ks) {
                        uint4 bv = ldsm_x4(b_s + bOffF[t] + ks * 32);
                        #pragma unroll
                        for (int mi = 0; mi < 4; ++mi) {
                            mma_f16(facc[mi][2 * t + 0], af[mi][ks], bv.x, bv.y);
                            mma_f16(facc[mi][2 * t + 1], af[mi][ks], bv.z, bv.w);
                        }
                    }
                }
            }
            if (jglob <= 29) {
                copy1F(jglob * 2 + 4);
                copy1F(jglob * 2 + 5);
                COMMIT();
            }
        }

        #pragma unroll
        for (int mi = 0; mi < 4; ++mi) {
            #pragma unroll
            for (int ni = 0; ni < 4; ++ni) {
                const int col = nc * 128 + nw * 32 + ni * 8 + 2 * (lane & 3);
                const float b0 = bias_s[col], b1 = bias_s[col + 1];
                #pragma unroll
                for (int e = 0; e < 2; ++e) {
                    const int row = mw * 64 + mi * 16 + e * 8 + (lane >> 2);
                    float v0 = fmaxf(facc[mi][ni][2 * e + 0] + b0, 0.0f);
                    float v1 = fmaxf(facc[mi][ni][2 * e + 1] + b1, 0.0f);
                    *(float2*)(g_R + (size_t)(tok0 + row) * 512 + col) =
                        make_float2(v0, v1);
                }
            }
        }
    }
}

// ---------------- scatter: out[t,:] = R[slot[ids[t]],:] ----------------
__global__ void __launch_bounds__(256) scatter_out(const int* __restrict__ ids,
                                                   float* __restrict__ out) {
    size_t i = (size_t)blockIdx.x * 256 + threadIdx.x;   // NTOK*128 threads
    int token = (int)(i >> 7);
    int c4 = (int)(i & 127);
    int slot = g_slot[ids[token]];
    float4 v = *(const float4*)(g_R + (size_t)slot * 512 + c4 * 4);
    __stcs(((float4*)out) + i, v);   // streaming store: don't pollute L2
}

// ---------------- launch ----------------
extern "C" void kernel_launch(void* const* d_in, const int* in_sizes, int n_in,
                              void* d_out, int out_size) {
    (void)in_sizes; (void)n_in; (void)out_size;
    const int*   ids  = (const int*)d_in[0];
    const float* emb  = (const float*)d_in[1];
    const float* Wih0 = (const float*)d_in[2];
    const float* bih0 = (const float*)d_in[4];
    const float* bhh0 = (const float*)d_in[5];
    const float* Wih1 = (const float*)d_in[6];
    const float* bih1 = (const float*)d_in[8];
    const float* bhh1 = (const float*)d_in[9];
    const float* Wlin = (const float*)d_in[10];
    const float* blin = (const float*)d_in[11];
    float* out = (float*)d_out;

    cudaFuncSetAttribute(fused_gemm,
                         cudaFuncAttributeMaxDynamicSharedMemorySize, L_SMEM);

    reset_k<<<(VOCABP + 255) / 256, 256>>>();
    mark_k<<<NTOK / 256, 256>>>(ids);
    compact_k<<<(VOCABP + 255) / 256, 256>>>();
    f2h_all<<<(589824 + 255) / 256, 256>>>(Wih0, Wih1, Wlin);
    emb_gather<<<(VOCABP * 64) / 256, 256>>>(emb);
    fused_gemm<<<NVT, THREADS, L_SMEM>>>(bih0, bhh0, bih1, bhh1, blin);
    scatter_out<<<(NTOK * 128) / 256, 256>>>(ids, out);
}

// round 13
// speedup vs baseline: 1.2134x; 1.0665x over previous
#include <cuda_runtime.h>
#include <cuda_fp16.h>
#include <cstdint>

#define NTOK    65536
#define VOCAB   50257
#define VOCABP  50304                 // 393 * 128
#define NVT     (VOCABP / 128)        // 393 tiles
#define THREADS 256

// ---------------- scratch (device globals: allocation-free) ----------------
__device__ __half g_Hv[(size_t)VOCABP * 512];    // activations (in-place per phase)
__device__ float  g_R[(size_t)VOCABP * 512];     // final table
__device__ __half g_W0h[2048 * 512];
__device__ __half g_W1h[2048 * 512];
__device__ __half g_Wlh[512 * 512];
__device__ int    g_used[VOCABP];
__device__ int    g_slot[VOCABP];
__device__ int    g_uid[VOCABP];
__device__ int    g_nuniq;

// ---------------- helpers ----------------
__device__ __forceinline__ uint32_t smem_u32(const void* p) {
    uint32_t a;
    asm("{ .reg .u64 t; cvta.to.shared.u64 t, %1; cvt.u32.u64 %0, t; }"
        : "=r"(a) : "l"(p));
    return a;
}
__device__ __forceinline__ void cp16(uint32_t dst, const void* src) {
    asm volatile("cp.async.cg.shared.global [%0], [%1], 16;"
                 :: "r"(dst), "l"(src));
}
__device__ __forceinline__ uint4 ldsm_x4(uint32_t a) {
    uint4 v;
    asm volatile("ldmatrix.sync.aligned.m8n8.x4.shared.b16 {%0,%1,%2,%3}, [%4];"
                 : "=r"(v.x), "=r"(v.y), "=r"(v.z), "=r"(v.w) : "r"(a));
    return v;
}
__device__ __forceinline__ void mma_f16(float c[4], const uint4& a,
                                        uint32_t b0, uint32_t b1) {
    asm volatile(
        "mma.sync.aligned.m16n8k16.row.col.f32.f16.f16.f32 "
        "{%0,%1,%2,%3}, {%4,%5,%6,%7}, {%8,%9}, {%0,%1,%2,%3};"
        : "+f"(c[0]), "+f"(c[1]), "+f"(c[2]), "+f"(c[3])
        : "r"(a.x), "r"(a.y), "r"(a.z), "r"(a.w), "r"(b0), "r"(b1));
}
// sig(x)*tanh(y) = (1 - e^{-2y}) / ((1 + e^{-x}) (1 + e^{-2y}))
__device__ __forceinline__ float sigtanh(float x, float y) {
    float ex = __expf(-x);
    float ey = __expf(-2.0f * y);
    return __fdividef(1.0f - ey, (1.0f + ex) * (1.0f + ey));
}

// ---------------- dedup pipeline ----------------
__global__ void __launch_bounds__(256) reset_k() {
    int i = blockIdx.x * 256 + threadIdx.x;
    if (i < VOCABP) g_used[i] = 0;
    if (i == 0) g_nuniq = 0;
}
__global__ void __launch_bounds__(256) mark_k(const int* __restrict__ ids) {
    int t = blockIdx.x * 256 + threadIdx.x;
    if (t < NTOK) g_used[ids[t]] = 1;
}
__global__ void __launch_bounds__(256) compact_k() {
    int i = blockIdx.x * 256 + threadIdx.x;
    int used = (i < VOCABP) ? g_used[i] : 0;
    unsigned bal = __ballot_sync(0xffffffffu, used);
    int lane = threadIdx.x & 31, warp = threadIdx.x >> 5;
    __shared__ int wbase[8];
    __shared__ int bbase;
    if (lane == 0) wbase[warp] = __popc(bal);
    __syncthreads();
    if (threadIdx.x == 0) {
        int s = 0;
        #pragma unroll
        for (int w = 0; w < 8; ++w) { int c = wbase[w]; wbase[w] = s; s += c; }
        bbase = atomicAdd(&g_nuniq, s);
    }
    __syncthreads();
    if (used) {
        int rank = bbase + wbase[warp] + __popc(bal & ((1u << lane) - 1));
        g_slot[i] = rank;
        g_uid[rank] = i;
    }
}

// ---------------- prep: all f32 weights -> f16, one launch ----------------
__global__ void __launch_bounds__(256) f2h_all(const float* __restrict__ W0,
                                               const float* __restrict__ W1,
                                               const float* __restrict__ Wl) {
    int i = blockIdx.x * 256 + threadIdx.x;
    if (i >= 589824) return;
    const float* src; __half* dst; int off;
    if (i < 262144)      { src = W0; dst = g_W0h; off = i; }
    else if (i < 524288) { src = W1; dst = g_W1h; off = i - 262144; }
    else                 { src = Wl; dst = g_Wlh; off = i - 524288; }
    float4 v = ((const float4*)src)[off];
    __half2 a = __floats2half2_rn(v.x, v.y);
    __half2 b = __floats2half2_rn(v.z, v.w);
    uint2 u;
    u.x = *(uint32_t*)&a; u.y = *(uint32_t*)&b;
    *(uint2*)(dst + (size_t)off * 4) = u;
}

// ---------------- compacted emb gather -> f16 table ----------------
// Only rows < ceil128(nuniq) are ever read by the GEMM (later tiles early-exit);
// write zeros for boundary-tile tail rows, skip everything beyond.
__global__ void __launch_bounds__(256) emb_gather(const float* __restrict__ emb) {
    size_t i = (size_t)blockIdx.x * 256 + threadIdx.x;   // VOCABP*64 threads
    int row = (int)(i >> 6);
    const int nu = g_nuniq;
    const int lim = (nu + 127) & ~127;
    if (row >= lim) return;                   // never read — skip write
    int c = (int)(i & 63) * 8;
    uint4 u = make_uint4(0, 0, 0, 0);
    if (row < nu) {
        int id = g_uid[row];
        const float4* p = (const float4*)(emb + (size_t)id * 512 + c);
        float4 v0 = p[0], v1 = p[1];
        __half2 h0 = __floats2half2_rn(v0.x, v0.y);
        __half2 h1 = __floats2half2_rn(v0.z, v0.w);
        __half2 h2 = __floats2half2_rn(v1.x, v1.y);
        __half2 h3 = __floats2half2_rn(v1.z, v1.w);
        u.x = *(uint32_t*)&h0; u.y = *(uint32_t*)&h1;
        u.z = *(uint32_t*)&h2; u.w = *(uint32_t*)&h3;
    }
    *(uint4*)(g_Hv + i * 8) = u;
}

// ======= fused layer0 -> layer1 -> final, 128-row tile (R8 structure, verbatim) ====
// smem: A resident 128 x 1040B; B 3 stages x up to 192 x 80B; bias 3x512 f32
#define LA_STRIDE 1040
#define L_AOFF    0
#define L_BOFF    (128 * LA_STRIDE)            // 133120
#define L_BSTAGE  (192 * 80)                   // 15360 (layer); fin uses 128*80
#define F_BSTAGE  (128 * 80)                   // 10240
#define L_BIASOFF (L_BOFF + 3 * L_BSTAGE)      // 179200
#define L_SMEM    (L_BIASOFF + 3 * 512 * 4)    // 185344

__global__ void __launch_bounds__(THREADS, 1) fused_gemm(
    const float* __restrict__ bih0, const float* __restrict__ bhh0,
    const float* __restrict__ bih1, const float* __restrict__ bhh1,
    const float* __restrict__ blin)
{
    const size_t tok0 = (size_t)blockIdx.x * 128;
    if ((int)tok0 >= g_nuniq) return;

    extern __shared__ char smem[];
    const int tid  = threadIdx.x;
    const int lane = tid & 31, wid = tid >> 5;
    const int mw = wid >> 2, nw = wid & 3;      // 2 M-warps x 4 N-warps
    const uint32_t sb = smem_u32(smem);
    float* bias_s = (float*)(smem + L_BIASOFF);

    __half* Arows = g_Hv + tok0 * 512;          // this tile's activation rows

    // per-lane ldmatrix base addresses (A layout identical in all phases)
    const int within = lane & 7, grp = lane >> 3;
    uint32_t aBase[4];
    #pragma unroll
    for (int mi = 0; mi < 4; ++mi) {
        int m = mw * 64 + mi * 16 + within + 8 * (grp & 1);
        aBase[mi] = sb + L_AOFF + (uint32_t)m * LA_STRIDE + (grp >> 1) * 16;
    }
    uint32_t bBaseL[3];                         // layer phases: 3 gates x 16n
    #pragma unroll
    for (int g = 0; g < 3; ++g) {
        int n = g * 64 + nw * 16 + within + 8 * (grp >> 1);
        bBaseL[g] = (uint32_t)n * 80 + (grp & 1) * 16;
    }
    uint32_t bBaseF[2];                         // fin phase: 2 x 16n
    #pragma unroll
    for (int t = 0; t < 2; ++t) {
        int n = nw * 32 + t * 16 + within + 8 * (grp >> 1);
        bBaseF[t] = (uint32_t)n * 80 + (grp & 1) * 16;
    }

    // A resident load (32 x 16B per thread), committed with caller's B stage0
    auto loadA = [&]() {
        #pragma unroll
        for (int j = 0; j < 32; ++j) {
            int idx = tid + 256 * j;
            int r = idx >> 6, c16 = idx & 63;
            cp16(sb + L_AOFF + (uint32_t)r * LA_STRIDE + c16 * 16,
                 Arows + (size_t)r * 512 + c16 * 8);
        }
    };

    // ================= LSTM phases =================
    for (int L = 0; L < 2; ++L) {
        const __half* Wh   = L ? g_W1h : g_W0h;
        const float*  b_ih = L ? bih1 : bih0;
        const float*  b_hh = L ? bhh1 : bhh0;

        if (L) { __threadfence_block(); }       // own h STGs -> visible to own cp.async
        __syncthreads();                        // prev-phase smem reads done

        for (int j = tid; j < 512; j += THREADS) {
            bias_s[j]        = b_ih[j]        + b_hh[j];          // i
            bias_s[512 + j]  = b_ih[1024 + j] + b_hh[1024 + j];   // g
            bias_s[1024 + j] = b_ih[1536 + j] + b_hh[1536 + j];   // o
        }

        auto stage_copyB = [&](int stage, int ncc, int kc) {
            const uint32_t b_s = sb + L_BOFF + stage * L_BSTAGE;
            #pragma unroll
            for (int j = 0; j < 3; ++j) {
                int idx = tid + 256 * j;
                int n = idx >> 2, c8 = idx & 3;
                int gate = n >> 6, nn = n & 63;
                int grow = (gate + (gate > 0)) * 512 + ncc * 64 + nn; // skip f
                cp16(b_s + (uint32_t)n * 80 + c8 * 16,
                     Wh + (size_t)grow * 512 + kc * 32 + c8 * 8);
            }
            asm volatile("cp.async.commit_group;" ::: "memory");
        };

        loadA();
        stage_copyB(0, 0, 0);
        stage_copyB(1, 0, 1);

        float acc[3][4][2][4];

        for (int nc = 0; nc < 8; ++nc) {
            #pragma unroll
            for (int g = 0; g < 3; ++g)
                #pragma unroll
                for (int mi = 0; mi < 4; ++mi)
                    #pragma unroll
                    for (int ni = 0; ni < 2; ++ni)
                        #pragma unroll
                        for (int q = 0; q < 4; ++q) acc[g][mi][ni][q] = 0.0f;

            for (int kc = 0; kc < 16; ++kc) {
                if (kc < 15) asm volatile("cp.async.wait_group 1;" ::: "memory");
                else         asm volatile("cp.async.wait_group 0;" ::: "memory");
                __syncthreads();

                const uint32_t b_s = sb + L_BOFF + (kc % 3) * L_BSTAGE;

                uint4 af[4][2];
                #pragma unroll
                for (int mi = 0; mi < 4; ++mi)
                    #pragma unroll
                    for (int ks = 0; ks < 2; ++ks)
                        af[mi][ks] = ldsm_x4(aBase[mi] + (kc * 32 + ks * 16) * 2);

                #pragma unroll
                for (int g = 0; g < 3; ++g) {
                    #pragma unroll
                    for (int ks = 0; ks < 2; ++ks) {
                        uint4 bv = ldsm_x4(b_s + bBaseL[g] + ks * 32);
                        #pragma unroll
                        for (int mi = 0; mi < 4; ++mi) {
                            mma_f16(acc[g][mi][0], af[mi][ks], bv.x, bv.y);
                            mma_f16(acc[g][mi][1], af[mi][ks], bv.z, bv.w);
                        }
                    }
                }
                if (kc < 14) stage_copyB((kc + 2) % 3, nc, kc + 2);
            }
            __syncthreads();
            if (nc < 7) { stage_copyB(0, nc + 1, 0); stage_copyB(1, nc + 1, 1); }

            // epilogue: h = sig(o)*tanh( sig(i)*tanh(g) ), 6 MUFU per element
            #pragma unroll
            for (int mi = 0; mi < 4; ++mi) {
                #pragma unroll
                for (int ni = 0; ni < 2; ++ni) {
                    const int col = nc * 64 + nw * 16 + ni * 8 + 2 * (lane & 3);
                    const float bi0 = bias_s[col],        bi1 = bias_s[col + 1];
                    const float bg0 = bias_s[512 + col],  bg1 = bias_s[512 + col + 1];
                    const float bo0 = bias_s[1024 + col], bo1 = bias_s[1024 + col + 1];
                    #pragma unroll
                    for (int e = 0; e < 2; ++e) {
                        const int row = mw * 64 + mi * 16 + e * 8 + (lane >> 2);
                        float c0 = sigtanh(acc[0][mi][ni][2 * e + 0] + bi0,
                                           acc[1][mi][ni][2 * e + 0] + bg0);
                        float c1 = sigtanh(acc[0][mi][ni][2 * e + 1] + bi1,
                                           acc[1][mi][ni][2 * e + 1] + bg1);
                        float h0 = sigtanh(acc[2][mi][ni][2 * e + 0] + bo0, c0);
                        float h1 = sigtanh(acc[2][mi][ni][2 * e + 1] + bo1, c1);
                        *(__half2*)(Arows + (size_t)row * 512 + col) =
                            __floats2half2_rn(h0, h1);
                    }
                }
            }
        }
    }

    // ================= final linear phase =================
    __threadfence_block();
    __syncthreads();
    for (int j = tid; j < 512; j += THREADS) bias_s[j] = blin[j];

    auto stage_copyF = [&](int stage, int ncc, int kc) {
        const uint32_t b_s = sb + L_BOFF + stage * F_BSTAGE;
        #pragma unroll
        for (int j = 0; j < 2; ++j) {
            int idx = tid + 256 * j;
            int n = idx >> 2, c8 = idx & 3;
            int grow = ncc * 128 + n;
            cp16(b_s + (uint32_t)n * 80 + c8 * 16,
                 g_Wlh + (size_t)grow * 512 + kc * 32 + c8 * 8);
        }
        asm volatile("cp.async.commit_group;" ::: "memory");
    };

    loadA();
    stage_copyF(0, 0, 0);
    stage_copyF(1, 0, 1);

    float facc[4][4][4];

    for (int nc = 0; nc < 4; ++nc) {
        #pragma unroll
        for (int mi = 0; mi < 4; ++mi)
            #pragma unroll
            for (int ni = 0; ni < 4; ++ni)
                #pragma unroll
                for (int q = 0; q < 4; ++q) facc[mi][ni][q] = 0.0f;

        for (int kc = 0; kc < 16; ++kc) {
            if (kc < 15) asm volatile("cp.async.wait_group 1;" ::: "memory");
            else         asm volatile("cp.async.wait_group 0;" ::: "memory");
            __syncthreads();

            const uint32_t b_s = sb + L_BOFF + (kc % 3) * F_BSTAGE;

            uint4 af[4][2];
            #pragma unroll
            for (int mi = 0; mi < 4; ++mi)
                #pragma unroll
                for (int ks = 0; ks < 2; ++ks)
                    af[mi][ks] = ldsm_x4(aBase[mi] + (kc * 32 + ks * 16) * 2);

            #pragma unroll
            for (int t = 0; t < 2; ++t) {
                #pragma unroll
                for (int ks = 0; ks < 2; ++ks) {
                    uint4 bv = ldsm_x4(b_s + bBaseF[t] + ks * 32);
                    #pragma unroll
                    for (int mi = 0; mi < 4; ++mi) {
                        mma_f16(facc[mi][2 * t + 0], af[mi][ks], bv.x, bv.y);
                        mma_f16(facc[mi][2 * t + 1], af[mi][ks], bv.z, bv.w);
                    }
                }
            }
            if (kc < 14) stage_copyF((kc + 2) % 3, nc, kc + 2);
        }
        __syncthreads();
        if (nc < 3) { stage_copyF(0, nc + 1, 0); stage_copyF(1, nc + 1, 1); }

        #pragma unroll
        for (int mi = 0; mi < 4; ++mi) {
            #pragma unroll
            for (int ni = 0; ni < 4; ++ni) {
                const int col = nc * 128 + nw * 32 + ni * 8 + 2 * (lane & 3);
                const float b0 = bias_s[col], b1 = bias_s[col + 1];
                #pragma unroll
                for (int e = 0; e < 2; ++e) {
                    const int row = mw * 64 + mi * 16 + e * 8 + (lane >> 2);
                    float v0 = fmaxf(facc[mi][ni][2 * e + 0] + b0, 0.0f);
                    float v1 = fmaxf(facc[mi][ni][2 * e + 1] + b1, 0.0f);
                    *(float2*)(g_R + (tok0 + row) * 512 + col) =
                        make_float2(v0, v1);
                }
            }
        }
    }
}

// ---------------- scatter: out[t,:] = R[slot[ids[t]],:] ----------------
__global__ void __launch_bounds__(256) scatter_out(const int* __restrict__ ids,
                                                   float* __restrict__ out) {
    size_t i = (size_t)blockIdx.x * 256 + threadIdx.x;   // NTOK*128 threads
    int token = (int)(i >> 7);
    int c4 = (int)(i & 127);
    int slot = g_slot[ids[token]];
    float4 v = *(const float4*)(g_R + (size_t)slot * 512 + c4 * 4);
    __stcs(((float4*)out) + i, v);   // streaming store: don't pollute L2
}

// ---------------- launch ----------------
extern "C" void kernel_launch(void* const* d_in, const int* in_sizes, int n_in,
                              void* d_out, int out_size) {
    (void)in_sizes; (void)n_in; (void)out_size;
    const int*   ids  = (const int*)d_in[0];
    const float* emb  = (const float*)d_in[1];
    const float* Wih0 = (const float*)d_in[2];
    const float* bih0 = (const float*)d_in[4];
    const float* bhh0 = (const float*)d_in[5];
    const float* Wih1 = (const float*)d_in[6];
    const float* bih1 = (const float*)d_in[8];
    const float* bhh1 = (const float*)d_in[9];
    const float* Wlin = (const float*)d_in[10];
    const float* blin = (const float*)d_in[11];
    float* out = (float*)d_out;

    cudaFuncSetAttribute(fused_gemm,
                         cudaFuncAttributeMaxDynamicSharedMemorySize, L_SMEM);

    reset_k<<<(VOCABP + 255) / 256, 256>>>();
    mark_k<<<NTOK / 256, 256>>>(ids);
    compact_k<<<(VOCABP + 255) / 256, 256>>>();
    f2h_all<<<(589824 + 255) / 256, 256>>>(Wih0, Wih1, Wlin);
    emb_gather<<<(VOCABP * 64) / 256, 256>>>(emb);
    fused_gemm<<<NVT, THREADS, L_SMEM>>>(bih0, bhh0, bih1, bhh1, blin);
    scatter_out<<<(NTOK * 128) / 256, 256>>>(ids, out);
}

// round 14
// speedup vs baseline: 1.2485x; 1.0290x over previous
#include <cuda_runtime.h>
#include <cuda_fp16.h>
#include <cstdint>

#define NTOK    65536
#define VOCAB   50257
#define VOCABP  50304                 // 393 * 128
#define NVT     (VOCABP / 128)        // 393 tiles
#define THREADS 256

// ---------------- scratch (device globals: allocation-free) ----------------
__device__ __half g_Hv[(size_t)VOCABP * 512];    // activations (in-place per phase)
__device__ float  g_R[(size_t)VOCABP * 512];     // final table
__device__ __half g_W0h[2048 * 512];
__device__ __half g_W1h[2048 * 512];
__device__ __half g_Wlh[512 * 512];
__device__ int    g_used[VOCABP];
__device__ int    g_slot[VOCABP];
__device__ int    g_uid[VOCABP];
__device__ int    g_nuniq;

// ---------------- helpers ----------------
__device__ __forceinline__ uint32_t smem_u32(const void* p) {
    uint32_t a;
    asm("{ .reg .u64 t; cvta.to.shared.u64 t, %1; cvt.u32.u64 %0, t; }"
        : "=r"(a) : "l"(p));
    return a;
}
__device__ __forceinline__ void cp16(uint32_t dst, const void* src) {
    asm volatile("cp.async.cg.shared.global [%0], [%1], 16;"
                 :: "r"(dst), "l"(src));
}
__device__ __forceinline__ uint4 ldsm_x4(uint32_t a) {
    uint4 v;
    asm volatile("ldmatrix.sync.aligned.m8n8.x4.shared.b16 {%0,%1,%2,%3}, [%4];"
                 : "=r"(v.x), "=r"(v.y), "=r"(v.z), "=r"(v.w) : "r"(a));
    return v;
}
__device__ __forceinline__ void mma_f16(float c[4], const uint4& a,
                                        uint32_t b0, uint32_t b1) {
    asm volatile(
        "mma.sync.aligned.m16n8k16.row.col.f32.f16.f16.f32 "
        "{%0,%1,%2,%3}, {%4,%5,%6,%7}, {%8,%9}, {%0,%1,%2,%3};"
        : "+f"(c[0]), "+f"(c[1]), "+f"(c[2]), "+f"(c[3])
        : "r"(a.x), "r"(a.y), "r"(a.z), "r"(a.w), "r"(b0), "r"(b1));
}
__device__ __forceinline__ float tanh_a(float x) {
    float y;
    asm("tanh.approx.f32 %0, %1;" : "=f"(y) : "f"(x));
    return y;
}
// sig(x)*tanh(y) = (0.5*tanh(x/2) + 0.5) * tanh(y)   -- 2 MUFU.TANH
__device__ __forceinline__ float sigtanh(float x, float y) {
    float s = fmaf(0.5f, tanh_a(0.5f * x), 0.5f);
    return s * tanh_a(y);
}

// ---------------- dedup pipeline ----------------
__global__ void __launch_bounds__(256) reset_k() {
    int i = blockIdx.x * 256 + threadIdx.x;
    if (i < VOCABP) g_used[i] = 0;
    if (i == 0) g_nuniq = 0;
}
__global__ void __launch_bounds__(256) mark_k(const int* __restrict__ ids) {
    int t = blockIdx.x * 256 + threadIdx.x;
    if (t < NTOK) g_used[ids[t]] = 1;
}
__global__ void __launch_bounds__(256) compact_k() {
    int i = blockIdx.x * 256 + threadIdx.x;
    int used = (i < VOCABP) ? g_used[i] : 0;
    unsigned bal = __ballot_sync(0xffffffffu, used);
    int lane = threadIdx.x & 31, warp = threadIdx.x >> 5;
    __shared__ int wbase[8];
    __shared__ int bbase;
    if (lane == 0) wbase[warp] = __popc(bal);
    __syncthreads();
    if (threadIdx.x == 0) {
        int s = 0;
        #pragma unroll
        for (int w = 0; w < 8; ++w) { int c = wbase[w]; wbase[w] = s; s += c; }
        bbase = atomicAdd(&g_nuniq, s);
    }
    __syncthreads();
    if (used) {
        int rank = bbase + wbase[warp] + __popc(bal & ((1u << lane) - 1));
        g_slot[i] = rank;
        g_uid[rank] = i;
    }
}

// ---------------- prep: all f32 weights -> f16, one launch ----------------
__global__ void __launch_bounds__(256) f2h_all(const float* __restrict__ W0,
                                               const float* __restrict__ W1,
                                               const float* __restrict__ Wl) {
    int i = blockIdx.x * 256 + threadIdx.x;
    if (i >= 589824) return;
    const float* src; __half* dst; int off;
    if (i < 262144)      { src = W0; dst = g_W0h; off = i; }
    else if (i < 524288) { src = W1; dst = g_W1h; off = i - 262144; }
    else                 { src = Wl; dst = g_Wlh; off = i - 524288; }
    float4 v = ((const float4*)src)[off];
    __half2 a = __floats2half2_rn(v.x, v.y);
    __half2 b = __floats2half2_rn(v.z, v.w);
    uint2 u;
    u.x = *(uint32_t*)&a; u.y = *(uint32_t*)&b;
    *(uint2*)(dst + (size_t)off * 4) = u;
}

// ---------------- compacted emb gather -> f16 table ----------------
__global__ void __launch_bounds__(256) emb_gather(const float* __restrict__ emb) {
    size_t i = (size_t)blockIdx.x * 256 + threadIdx.x;   // VOCABP*64 threads
    int row = (int)(i >> 6);
    const int nu = g_nuniq;
    const int lim = (nu + 127) & ~127;
    if (row >= lim) return;                   // never read — skip write
    int c = (int)(i & 63) * 8;
    uint4 u = make_uint4(0, 0, 0, 0);
    if (row < nu) {
        int id = g_uid[row];
        const float4* p = (const float4*)(emb + (size_t)id * 512 + c);
        float4 v0 = p[0], v1 = p[1];
        __half2 h0 = __floats2half2_rn(v0.x, v0.y);
        __half2 h1 = __floats2half2_rn(v0.z, v0.w);
        __half2 h2 = __floats2half2_rn(v1.x, v1.y);
        __half2 h3 = __floats2half2_rn(v1.z, v1.w);
        u.x = *(uint32_t*)&h0; u.y = *(uint32_t*)&h1;
        u.z = *(uint32_t*)&h2; u.w = *(uint32_t*)&h3;
    }
    *(uint4*)(g_Hv + i * 8) = u;
}

// ======= fused layer0 -> layer1 -> final, 128-row tile (R8 structure, verbatim) ====
// smem: A resident 128 x 1040B; B 3 stages x up to 192 x 80B; bias 3x512 f32
#define LA_STRIDE 1040
#define L_AOFF    0
#define L_BOFF    (128 * LA_STRIDE)            // 133120
#define L_BSTAGE  (192 * 80)                   // 15360 (layer); fin uses 128*80
#define F_BSTAGE  (128 * 80)                   // 10240
#define L_BIASOFF (L_BOFF + 3 * L_BSTAGE)      // 179200
#define L_SMEM    (L_BIASOFF + 3 * 512 * 4)    // 185344

__global__ void __launch_bounds__(THREADS, 1) fused_gemm(
    const float* __restrict__ bih0, const float* __restrict__ bhh0,
    const float* __restrict__ bih1, const float* __restrict__ bhh1,
    const float* __restrict__ blin)
{
    const size_t tok0 = (size_t)blockIdx.x * 128;
    if ((int)tok0 >= g_nuniq) return;

    extern __shared__ char smem[];
    const int tid  = threadIdx.x;
    const int lane = tid & 31, wid = tid >> 5;
    const int mw = wid >> 2, nw = wid & 3;      // 2 M-warps x 4 N-warps
    const uint32_t sb = smem_u32(smem);
    float* bias_s = (float*)(smem + L_BIASOFF);

    __half* Arows = g_Hv + tok0 * 512;          // this tile's activation rows

    // per-lane ldmatrix base addresses (A layout identical in all phases)
    const int within = lane & 7, grp = lane >> 3;
    uint32_t aBase[4];
    #pragma unroll
    for (int mi = 0; mi < 4; ++mi) {
        int m = mw * 64 + mi * 16 + within + 8 * (grp & 1);
        aBase[mi] = sb + L_AOFF + (uint32_t)m * LA_STRIDE + (grp >> 1) * 16;
    }
    uint32_t bBaseL[3];                         // layer phases: 3 gates x 16n
    #pragma unroll
    for (int g = 0; g < 3; ++g) {
        int n = g * 64 + nw * 16 + within + 8 * (grp >> 1);
        bBaseL[g] = (uint32_t)n * 80 + (grp & 1) * 16;
    }
    uint32_t bBaseF[2];                         // fin phase: 2 x 16n
    #pragma unroll
    for (int t = 0; t < 2; ++t) {
        int n = nw * 32 + t * 16 + within + 8 * (grp >> 1);
        bBaseF[t] = (uint32_t)n * 80 + (grp & 1) * 16;
    }

    // A resident load (32 x 16B per thread), committed with caller's B stage0
    auto loadA = [&]() {
        #pragma unroll
        for (int j = 0; j < 32; ++j) {
            int idx = tid + 256 * j;
            int r = idx >> 6, c16 = idx & 63;
            cp16(sb + L_AOFF + (uint32_t)r * LA_STRIDE + c16 * 16,
                 Arows + (size_t)r * 512 + c16 * 8);
        }
    };

    // ================= LSTM phases =================
    for (int L = 0; L < 2; ++L) {
        const __half* Wh   = L ? g_W1h : g_W0h;
        const float*  b_ih = L ? bih1 : bih0;
        const float*  b_hh = L ? bhh1 : bhh0;

        if (L) { __threadfence_block(); }       // own h STGs -> visible to own cp.async
        __syncthreads();                        // prev-phase smem reads done

        for (int j = tid; j < 512; j += THREADS) {
            bias_s[j]        = b_ih[j]        + b_hh[j];          // i
            bias_s[512 + j]  = b_ih[1024 + j] + b_hh[1024 + j];   // g
            bias_s[1024 + j] = b_ih[1536 + j] + b_hh[1536 + j];   // o
        }

        auto stage_copyB = [&](int stage, int ncc, int kc) {
            const uint32_t b_s = sb + L_BOFF + stage * L_BSTAGE;
            #pragma unroll
            for (int j = 0; j < 3; ++j) {
                int idx = tid + 256 * j;
                int n = idx >> 2, c8 = idx & 3;
                int gate = n >> 6, nn = n & 63;
                int grow = (gate + (gate > 0)) * 512 + ncc * 64 + nn; // skip f
                cp16(b_s + (uint32_t)n * 80 + c8 * 16,
                     Wh + (size_t)grow * 512 + kc * 32 + c8 * 8);
            }
            asm volatile("cp.async.commit_group;" ::: "memory");
        };

        loadA();
        stage_copyB(0, 0, 0);
        stage_copyB(1, 0, 1);

        float acc[3][4][2][4];

        for (int nc = 0; nc < 8; ++nc) {
            #pragma unroll
            for (int g = 0; g < 3; ++g)
                #pragma unroll
                for (int mi = 0; mi < 4; ++mi)
                    #pragma unroll
                    for (int ni = 0; ni < 2; ++ni)
                        #pragma unroll
                        for (int q = 0; q < 4; ++q) acc[g][mi][ni][q] = 0.0f;

            for (int kc = 0; kc < 16; ++kc) {
                if (kc < 15) asm volatile("cp.async.wait_group 1;" ::: "memory");
                else         asm volatile("cp.async.wait_group 0;" ::: "memory");
                __syncthreads();

                const uint32_t b_s = sb + L_BOFF + (kc % 3) * L_BSTAGE;

                uint4 af[4][2];
                #pragma unroll
                for (int mi = 0; mi < 4; ++mi)
                    #pragma unroll
                    for (int ks = 0; ks < 2; ++ks)
                        af[mi][ks] = ldsm_x4(aBase[mi] + (kc * 32 + ks * 16) * 2);

                #pragma unroll
                for (int g = 0; g < 3; ++g) {
                    #pragma unroll
                    for (int ks = 0; ks < 2; ++ks) {
                        uint4 bv = ldsm_x4(b_s + bBaseL[g] + ks * 32);
                        #pragma unroll
                        for (int mi = 0; mi < 4; ++mi) {
                            mma_f16(acc[g][mi][0], af[mi][ks], bv.x, bv.y);
                            mma_f16(acc[g][mi][1], af[mi][ks], bv.z, bv.w);
                        }
                    }
                }
                if (kc < 14) stage_copyB((kc + 2) % 3, nc, kc + 2);
            }
            __syncthreads();
            if (nc < 7) { stage_copyB(0, nc + 1, 0); stage_copyB(1, nc + 1, 1); }

            // epilogue: h = sig(o)*tanh( sig(i)*tanh(g) ), 4 MUFU.TANH per element
            #pragma unroll
            for (int mi = 0; mi < 4; ++mi) {
                #pragma unroll
                for (int ni = 0; ni < 2; ++ni) {
                    const int col = nc * 64 + nw * 16 + ni * 8 + 2 * (lane & 3);
                    const float bi0 = bias_s[col],        bi1 = bias_s[col + 1];
                    const float bg0 = bias_s[512 + col],  bg1 = bias_s[512 + col + 1];
                    const float bo0 = bias_s[1024 + col], bo1 = bias_s[1024 + col + 1];
                    #pragma unroll
                    for (int e = 0; e < 2; ++e) {
                        const int row = mw * 64 + mi * 16 + e * 8 + (lane >> 2);
                        float c0 = sigtanh(acc[0][mi][ni][2 * e + 0] + bi0,
                                           acc[1][mi][ni][2 * e + 0] + bg0);
                        float c1 = sigtanh(acc[0][mi][ni][2 * e + 1] + bi1,
                                           acc[1][mi][ni][2 * e + 1] + bg1);
                        float h0 = sigtanh(acc[2][mi][ni][2 * e + 0] + bo0, c0);
                        float h1 = sigtanh(acc[2][mi][ni][2 * e + 1] + bo1, c1);
                        *(__half2*)(Arows + (size_t)row * 512 + col) =
                            __floats2half2_rn(h0, h1);
                    }
                }
            }
        }
    }

    // ================= final linear phase =================
    __threadfence_block();
    __syncthreads();
    for (int j = tid; j < 512; j += THREADS) bias_s[j] = blin[j];

    auto stage_copyF = [&](int stage, int ncc, int kc) {
        const uint32_t b_s = sb + L_BOFF + stage * F_BSTAGE;
        #pragma unroll
        for (int j = 0; j < 2; ++j) {
            int idx = tid + 256 * j;
            int n = idx >> 2, c8 = idx & 3;
            int grow = ncc * 128 + n;
            cp16(b_s + (uint32_t)n * 80 + c8 * 16,
                 g_Wlh + (size_t)grow * 512 + kc * 32 + c8 * 8);
        }
        asm volatile("cp.async.commit_group;" ::: "memory");
    };

    loadA();
    stage_copyF(0, 0, 0);
    stage_copyF(1, 0, 1);

    float facc[4][4][4];

    for (int nc = 0; nc < 4; ++nc) {
        #pragma unroll
        for (int mi = 0; mi < 4; ++mi)
            #pragma unroll
            for (int ni = 0; ni < 4; ++ni)
                #pragma unroll
                for (int q = 0; q < 4; ++q) facc[mi][ni][q] = 0.0f;

        for (int kc = 0; kc < 16; ++kc) {
            if (kc < 15) asm volatile("cp.async.wait_group 1;" ::: "memory");
            else         asm volatile("cp.async.wait_group 0;" ::: "memory");
            __syncthreads();

            const uint32_t b_s = sb + L_BOFF + (kc % 3) * F_BSTAGE;

            uint4 af[4][2];
            #pragma unroll
            for (int mi = 0; mi < 4; ++mi)
                #pragma unroll
                for (int ks = 0; ks < 2; ++ks)
                    af[mi][ks] = ldsm_x4(aBase[mi] + (kc * 32 + ks * 16) * 2);

            #pragma unroll
            for (int t = 0; t < 2; ++t) {
                #pragma unroll
                for (int ks = 0; ks < 2; ++ks) {
                    uint4 bv = ldsm_x4(b_s + bBaseF[t] + ks * 32);
                    #pragma unroll
                    for (int mi = 0; mi < 4; ++mi) {
                        mma_f16(facc[mi][2 * t + 0], af[mi][ks], bv.x, bv.y);
                        mma_f16(facc[mi][2 * t + 1], af[mi][ks], bv.z, bv.w);
                    }
                }
            }
            if (kc < 14) stage_copyF((kc + 2) % 3, nc, kc + 2);
        }
        __syncthreads();
        if (nc < 3) { stage_copyF(0, nc + 1, 0); stage_copyF(1, nc + 1, 1); }

        #pragma unroll
        for (int mi = 0; mi < 4; ++mi) {
            #pragma unroll
            for (int ni = 0; ni < 4; ++ni) {
                const int col = nc * 128 + nw * 32 + ni * 8 + 2 * (lane & 3);
                const float b0 = bias_s[col], b1 = bias_s[col + 1];
                #pragma unroll
                for (int e = 0; e < 2; ++e) {
                    const int row = mw * 64 + mi * 16 + e * 8 + (lane >> 2);
                    float v0 = fmaxf(facc[mi][ni][2 * e + 0] + b0, 0.0f);
                    float v1 = fmaxf(facc[mi][ni][2 * e + 1] + b1, 0.0f);
                    *(float2*)(g_R + (tok0 + row) * 512 + col) =
                        make_float2(v0, v1);
                }
            }
        }
    }
}

// ---------------- scatter: out[t,:] = R[slot[ids[t]],:] ----------------
__global__ void __launch_bounds__(256) scatter_out(const int* __restrict__ ids,
                                                   float* __restrict__ out) {
    size_t i = (size_t)blockIdx.x * 256 + threadIdx.x;   // NTOK*128 threads
    int token = (int)(i >> 7);
    int c4 = (int)(i & 127);
    int slot = g_slot[ids[token]];
    float4 v = *(const float4*)(g_R + (size_t)slot * 512 + c4 * 4);
    __stcs(((float4*)out) + i, v);   // streaming store: don't pollute L2
}

// ---------------- launch ----------------
extern "C" void kernel_launch(void* const* d_in, const int* in_sizes, int n_in,
                              void* d_out, int out_size) {
    (void)in_sizes; (void)n_in; (void)out_size;
    const int*   ids  = (const int*)d_in[0];
    const float* emb  = (const float*)d_in[1];
    const float* Wih0 = (const float*)d_in[2];
    const float* bih0 = (const float*)d_in[4];
    const float* bhh0 = (const float*)d_in[5];
    const float* Wih1 = (const float*)d_in[6];
    const float* bih1 = (const float*)d_in[8];
    const float* bhh1 = (const float*)d_in[9];
    const float* Wlin = (const float*)d_in[10];
    const float* blin = (const float*)d_in[11];
    float* out = (float*)d_out;

    cudaFuncSetAttribute(fused_gemm,
                         cudaFuncAttributeMaxDynamicSharedMemorySize, L_SMEM);

    reset_k<<<(VOCABP + 255) / 256, 256>>>();
    mark_k<<<NTOK / 256, 256>>>(ids);
    compact_k<<<(VOCABP + 255) / 256, 256>>>();
    f2h_all<<<(589824 + 255) / 256, 256>>>(Wih0, Wih1, Wlin);
    emb_gather<<<(VOCABP * 64) / 256, 256>>>(emb);
    fused_gemm<<<NVT, THREADS, L_SMEM>>>(bih0, bhh0, bih1, bhh1, blin);
    scatter_out<<<(NTOK * 128) / 256, 256>>>(ids, out);
}

// round 15
// speedup vs baseline: 1.2966x; 1.0385x over previous
#include <cuda_runtime.h>
#include <cuda_fp16.h>
#include <cstdint>

#define NTOK    65536
#define VOCAB   50257
#define VOCABP  50304                 // 393 * 128
#define NVT     (VOCABP / 128)        // 393 tiles
#define THREADS 256

// ---------------- scratch (device globals: allocation-free) ----------------
__device__ __half g_Hv[(size_t)VOCABP * 512];    // activations (in-place per phase)
__device__ __half g_Rh[(size_t)VOCABP * 512];    // final table (f16)
__device__ __half g_W0h[2048 * 512];
__device__ __half g_W1h[2048 * 512];
__device__ __half g_Wlh[512 * 512];
__device__ int    g_used[VOCABP];
__device__ int    g_slot[VOCABP];
__device__ int    g_uid[VOCABP];
__device__ int    g_nuniq;

// ---------------- helpers ----------------
__device__ __forceinline__ uint32_t smem_u32(const void* p) {
    uint32_t a;
    asm("{ .reg .u64 t; cvta.to.shared.u64 t, %1; cvt.u32.u64 %0, t; }"
        : "=r"(a) : "l"(p));
    return a;
}
__device__ __forceinline__ void cp16(uint32_t dst, const void* src) {
    asm volatile("cp.async.cg.shared.global [%0], [%1], 16;"
                 :: "r"(dst), "l"(src));
}
__device__ __forceinline__ uint4 ldsm_x4(uint32_t a) {
    uint4 v;
    asm volatile("ldmatrix.sync.aligned.m8n8.x4.shared.b16 {%0,%1,%2,%3}, [%4];"
                 : "=r"(v.x), "=r"(v.y), "=r"(v.z), "=r"(v.w) : "r"(a));
    return v;
}
__device__ __forceinline__ void mma_f16(float c[4], const uint4& a,
                                        uint32_t b0, uint32_t b1) {
    asm volatile(
        "mma.sync.aligned.m16n8k16.row.col.f32.f16.f16.f32 "
        "{%0,%1,%2,%3}, {%4,%5,%6,%7}, {%8,%9}, {%0,%1,%2,%3};"
        : "+f"(c[0]), "+f"(c[1]), "+f"(c[2]), "+f"(c[3])
        : "r"(a.x), "r"(a.y), "r"(a.z), "r"(a.w), "r"(b0), "r"(b1));
}
__device__ __forceinline__ float tanh_a(float x) {
    float y;
    asm("tanh.approx.f32 %0, %1;" : "=f"(y) : "f"(x));
    return y;
}
// sig(x)*tanh(y) = (0.5*tanh(x/2) + 0.5) * tanh(y)   -- 2 MUFU.TANH
__device__ __forceinline__ float sigtanh(float x, float y) {
    float s = fmaf(0.5f, tanh_a(0.5f * x), 0.5f);
    return s * tanh_a(y);
}

// ---------------- dedup pipeline ----------------
__global__ void __launch_bounds__(256) mark_k(const int* __restrict__ ids) {
    int t = blockIdx.x * 256 + threadIdx.x;
    if (t < NTOK) g_used[ids[t]] = 1;
}
__global__ void __launch_bounds__(256) compact_k() {
    int i = blockIdx.x * 256 + threadIdx.x;
    int used = (i < VOCABP) ? g_used[i] : 0;
    unsigned bal = __ballot_sync(0xffffffffu, used);
    int lane = threadIdx.x & 31, warp = threadIdx.x >> 5;
    __shared__ int wbase[8];
    __shared__ int bbase;
    if (lane == 0) wbase[warp] = __popc(bal);
    __syncthreads();
    if (threadIdx.x == 0) {
        int s = 0;
        #pragma unroll
        for (int w = 0; w < 8; ++w) { int c = wbase[w]; wbase[w] = s; s += c; }
        bbase = atomicAdd(&g_nuniq, s);
    }
    __syncthreads();
    if (used) {
        int rank = bbase + wbase[warp] + __popc(bal & ((1u << lane) - 1));
        g_slot[i] = rank;
        g_uid[rank] = i;
    }
}

// ---------------- prep: weights -> f16 + dedup reset, one launch ----------------
__global__ void __launch_bounds__(256) f2h_all(const float* __restrict__ W0,
                                               const float* __restrict__ W1,
                                               const float* __restrict__ Wl) {
    int i = blockIdx.x * 256 + threadIdx.x;
    // side duty: reset dedup state (indices beyond weight quads or overlapping — both fine)
    if (i < VOCABP) g_used[i] = 0;
    if (i == 0) g_nuniq = 0;
    if (i >= 589824) return;
    const float* src; __half* dst; int off;
    if (i < 262144)      { src = W0; dst = g_W0h; off = i; }
    else if (i < 524288) { src = W1; dst = g_W1h; off = i - 262144; }
    else                 { src = Wl; dst = g_Wlh; off = i - 524288; }
    float4 v = ((const float4*)src)[off];
    __half2 a = __floats2half2_rn(v.x, v.y);
    __half2 b = __floats2half2_rn(v.z, v.w);
    uint2 u;
    u.x = *(uint32_t*)&a; u.y = *(uint32_t*)&b;
    *(uint2*)(dst + (size_t)off * 4) = u;
}

// ---------------- compacted emb gather -> f16 table ----------------
__global__ void __launch_bounds__(256) emb_gather(const float* __restrict__ emb) {
    size_t i = (size_t)blockIdx.x * 256 + threadIdx.x;   // VOCABP*64 threads
    int row = (int)(i >> 6);
    const int nu = g_nuniq;
    const int lim = (nu + 127) & ~127;
    if (row >= lim) return;                   // never read — skip write
    int c = (int)(i & 63) * 8;
    uint4 u = make_uint4(0, 0, 0, 0);
    if (row < nu) {
        int id = g_uid[row];
        const float4* p = (const float4*)(emb + (size_t)id * 512 + c);
        float4 v0 = p[0], v1 = p[1];
        __half2 h0 = __floats2half2_rn(v0.x, v0.y);
        __half2 h1 = __floats2half2_rn(v0.z, v0.w);
        __half2 h2 = __floats2half2_rn(v1.x, v1.y);
        __half2 h3 = __floats2half2_rn(v1.z, v1.w);
        u.x = *(uint32_t*)&h0; u.y = *(uint32_t*)&h1;
        u.z = *(uint32_t*)&h2; u.w = *(uint32_t*)&h3;
    }
    *(uint4*)(g_Hv + i * 8) = u;
}

// ======= fused layer0 -> layer1 -> final, 128-row tile (R8 structure, verbatim) ====
// smem: A resident 128 x 1040B; B 3 stages x up to 192 x 80B; bias 3x512 f32
#define LA_STRIDE 1040
#define L_AOFF    0
#define L_BOFF    (128 * LA_STRIDE)            // 133120
#define L_BSTAGE  (192 * 80)                   // 15360 (layer); fin uses 128*80
#define F_BSTAGE  (128 * 80)                   // 10240
#define L_BIASOFF (L_BOFF + 3 * L_BSTAGE)      // 179200
#define L_SMEM    (L_BIASOFF + 3 * 512 * 4)    // 185344

__global__ void __launch_bounds__(THREADS, 1) fused_gemm(
    const float* __restrict__ bih0, const float* __restrict__ bhh0,
    const float* __restrict__ bih1, const float* __restrict__ bhh1,
    const float* __restrict__ blin)
{
    const size_t tok0 = (size_t)blockIdx.x * 128;
    if ((int)tok0 >= g_nuniq) return;

    extern __shared__ char smem[];
    const int tid  = threadIdx.x;
    const int lane = tid & 31, wid = tid >> 5;
    const int mw = wid >> 2, nw = wid & 3;      // 2 M-warps x 4 N-warps
    const uint32_t sb = smem_u32(smem);
    float* bias_s = (float*)(smem + L_BIASOFF);

    __half* Arows = g_Hv + tok0 * 512;          // this tile's activation rows

    // per-lane ldmatrix base addresses (A layout identical in all phases)
    const int within = lane & 7, grp = lane >> 3;
    uint32_t aBase[4];
    #pragma unroll
    for (int mi = 0; mi < 4; ++mi) {
        int m = mw * 64 + mi * 16 + within + 8 * (grp & 1);
        aBase[mi] = sb + L_AOFF + (uint32_t)m * LA_STRIDE + (grp >> 1) * 16;
    }
    uint32_t bBaseL[3];                         // layer phases: 3 gates x 16n
    #pragma unroll
    for (int g = 0; g < 3; ++g) {
        int n = g * 64 + nw * 16 + within + 8 * (grp >> 1);
        bBaseL[g] = (uint32_t)n * 80 + (grp & 1) * 16;
    }
    uint32_t bBaseF[2];                         // fin phase: 2 x 16n
    #pragma unroll
    for (int t = 0; t < 2; ++t) {
        int n = nw * 32 + t * 16 + within + 8 * (grp >> 1);
        bBaseF[t] = (uint32_t)n * 80 + (grp & 1) * 16;
    }

    // A resident load (32 x 16B per thread), committed with caller's B stage0
    auto loadA = [&]() {
        #pragma unroll
        for (int j = 0; j < 32; ++j) {
            int idx = tid + 256 * j;
            int r = idx >> 6, c16 = idx & 63;
            cp16(sb + L_AOFF + (uint32_t)r * LA_STRIDE + c16 * 16,
                 Arows + (size_t)r * 512 + c16 * 8);
        }
    };

    // ================= LSTM phases =================
    for (int L = 0; L < 2; ++L) {
        const __half* Wh   = L ? g_W1h : g_W0h;
        const float*  b_ih = L ? bih1 : bih0;
        const float*  b_hh = L ? bhh1 : bhh0;

        if (L) { __threadfence_block(); }       // own h STGs -> visible to own cp.async
        __syncthreads();                        // prev-phase smem reads done

        for (int j = tid; j < 512; j += THREADS) {
            bias_s[j]        = b_ih[j]        + b_hh[j];          // i
            bias_s[512 + j]  = b_ih[1024 + j] + b_hh[1024 + j];   // g
            bias_s[1024 + j] = b_ih[1536 + j] + b_hh[1536 + j];   // o
        }

        auto stage_copyB = [&](int stage, int ncc, int kc) {
            const uint32_t b_s = sb + L_BOFF + stage * L_BSTAGE;
            #pragma unroll
            for (int j = 0; j < 3; ++j) {
                int idx = tid + 256 * j;
                int n = idx >> 2, c8 = idx & 3;
                int gate = n >> 6, nn = n & 63;
                int grow = (gate + (gate > 0)) * 512 + ncc * 64 + nn; // skip f
                cp16(b_s + (uint32_t)n * 80 + c8 * 16,
                     Wh + (size_t)grow * 512 + kc * 32 + c8 * 8);
            }
            asm volatile("cp.async.commit_group;" ::: "memory");
        };

        loadA();
        stage_copyB(0, 0, 0);
        stage_copyB(1, 0, 1);

        float acc[3][4][2][4];

        for (int nc = 0; nc < 8; ++nc) {
            #pragma unroll
            for (int g = 0; g < 3; ++g)
                #pragma unroll
                for (int mi = 0; mi < 4; ++mi)
                    #pragma unroll
                    for (int ni = 0; ni < 2; ++ni)
                        #pragma unroll
                        for (int q = 0; q < 4; ++q) acc[g][mi][ni][q] = 0.0f;

            for (int kc = 0; kc < 16; ++kc) {
                if (kc < 15) asm volatile("cp.async.wait_group 1;" ::: "memory");
                else         asm volatile("cp.async.wait_group 0;" ::: "memory");
                __syncthreads();

                const uint32_t b_s = sb + L_BOFF + (kc % 3) * L_BSTAGE;

                uint4 af[4][2];
                #pragma unroll
                for (int mi = 0; mi < 4; ++mi)
                    #pragma unroll
                    for (int ks = 0; ks < 2; ++ks)
                        af[mi][ks] = ldsm_x4(aBase[mi] + (kc * 32 + ks * 16) * 2);

                #pragma unroll
                for (int g = 0; g < 3; ++g) {
                    #pragma unroll
                    for (int ks = 0; ks < 2; ++ks) {
                        uint4 bv = ldsm_x4(b_s + bBaseL[g] + ks * 32);
                        #pragma unroll
                        for (int mi = 0; mi < 4; ++mi) {
                            mma_f16(acc[g][mi][0], af[mi][ks], bv.x, bv.y);
                            mma_f16(acc[g][mi][1], af[mi][ks], bv.z, bv.w);
                        }
                    }
                }
                if (kc < 14) stage_copyB((kc + 2) % 3, nc, kc + 2);
            }
            __syncthreads();
            if (nc < 7) { stage_copyB(0, nc + 1, 0); stage_copyB(1, nc + 1, 1); }

            // epilogue: h = sig(o)*tanh( sig(i)*tanh(g) ), 4 MUFU.TANH per element
            #pragma unroll
            for (int mi = 0; mi < 4; ++mi) {
                #pragma unroll
                for (int ni = 0; ni < 2; ++ni) {
                    const int col = nc * 64 + nw * 16 + ni * 8 + 2 * (lane & 3);
                    const float bi0 = bias_s[col],        bi1 = bias_s[col + 1];
                    const float bg0 = bias_s[512 + col],  bg1 = bias_s[512 + col + 1];
                    const float bo0 = bias_s[1024 + col], bo1 = bias_s[1024 + col + 1];
                    #pragma unroll
                    for (int e = 0; e < 2; ++e) {
                        const int row = mw * 64 + mi * 16 + e * 8 + (lane >> 2);
                        float c0 = sigtanh(acc[0][mi][ni][2 * e + 0] + bi0,
                                           acc[1][mi][ni][2 * e + 0] + bg0);
                        float c1 = sigtanh(acc[0][mi][ni][2 * e + 1] + bi1,
                                           acc[1][mi][ni][2 * e + 1] + bg1);
                        float h0 = sigtanh(acc[2][mi][ni][2 * e + 0] + bo0, c0);
                        float h1 = sigtanh(acc[2][mi][ni][2 * e + 1] + bo1, c1);
                        *(__half2*)(Arows + (size_t)row * 512 + col) =
                            __floats2half2_rn(h0, h1);
                    }
                }
            }
        }
    }

    // ================= final linear phase =================
    __threadfence_block();
    __syncthreads();
    for (int j = tid; j < 512; j += THREADS) bias_s[j] = blin[j];

    auto stage_copyF = [&](int stage, int ncc, int kc) {
        const uint32_t b_s = sb + L_BOFF + stage * F_BSTAGE;
        #pragma unroll
        for (int j = 0; j < 2; ++j) {
            int idx = tid + 256 * j;
            int n = idx >> 2, c8 = idx & 3;
            int grow = ncc * 128 + n;
            cp16(b_s + (uint32_t)n * 80 + c8 * 16,
                 g_Wlh + (size_t)grow * 512 + kc * 32 + c8 * 8);
        }
        asm volatile("cp.async.commit_group;" ::: "memory");
    };

    loadA();
    stage_copyF(0, 0, 0);
    stage_copyF(1, 0, 1);

    float facc[4][4][4];

    for (int nc = 0; nc < 4; ++nc) {
        #pragma unroll
        for (int mi = 0; mi < 4; ++mi)
            #pragma unroll
            for (int ni = 0; ni < 4; ++ni)
                #pragma unroll
                for (int q = 0; q < 4; ++q) facc[mi][ni][q] = 0.0f;

        for (int kc = 0; kc < 16; ++kc) {
            if (kc < 15) asm volatile("cp.async.wait_group 1;" ::: "memory");
            else         asm volatile("cp.async.wait_group 0;" ::: "memory");
            __syncthreads();

            const uint32_t b_s = sb + L_BOFF + (kc % 3) * F_BSTAGE;

            uint4 af[4][2];
            #pragma unroll
            for (int mi = 0; mi < 4; ++mi)
                #pragma unroll
                for (int ks = 0; ks < 2; ++ks)
                    af[mi][ks] = ldsm_x4(aBase[mi] + (kc * 32 + ks * 16) * 2);

            #pragma unroll
            for (int t = 0; t < 2; ++t) {
                #pragma unroll
                for (int ks = 0; ks < 2; ++ks) {
                    uint4 bv = ldsm_x4(b_s + bBaseF[t] + ks * 32);
                    #pragma unroll
                    for (int mi = 0; mi < 4; ++mi) {
                        mma_f16(facc[mi][2 * t + 0], af[mi][ks], bv.x, bv.y);
                        mma_f16(facc[mi][2 * t + 1], af[mi][ks], bv.z, bv.w);
                    }
                }
            }
            if (kc < 14) stage_copyF((kc + 2) % 3, nc, kc + 2);
        }
        __syncthreads();
        if (nc < 3) { stage_copyF(0, nc + 1, 0); stage_copyF(1, nc + 1, 1); }

        #pragma unroll
        for (int mi = 0; mi < 4; ++mi) {
            #pragma unroll
            for (int ni = 0; ni < 4; ++ni) {
                const int col = nc * 128 + nw * 32 + ni * 8 + 2 * (lane & 3);
                const float b0 = bias_s[col], b1 = bias_s[col + 1];
                #pragma unroll
                for (int e = 0; e < 2; ++e) {
                    const int row = mw * 64 + mi * 16 + e * 8 + (lane >> 2);
                    float v0 = fmaxf(facc[mi][ni][2 * e + 0] + b0, 0.0f);
                    float v1 = fmaxf(facc[mi][ni][2 * e + 1] + b1, 0.0f);
                    *(__half2*)(g_Rh + (tok0 + row) * 512 + col) =
                        __floats2half2_rn(v0, v1);
                }
            }
        }
    }
}

// ---------------- scatter: out[t,:] = f32(Rh[slot[ids[t]],:]) ----------------
__global__ void __launch_bounds__(256) scatter_out(const int* __restrict__ ids,
                                                   float* __restrict__ out) {
    size_t i = (size_t)blockIdx.x * 256 + threadIdx.x;   // NTOK*128 threads
    int token = (int)(i >> 7);
    int c4 = (int)(i & 127);
    int slot = g_slot[ids[token]];
    uint2 u = *(const uint2*)(g_Rh + (size_t)slot * 512 + c4 * 4);
    __half2 h0 = *(__half2*)&u.x;
    __half2 h1 = *(__half2*)&u.y;
    float2 f0 = __half22float2(h0);
    float2 f1 = __half22float2(h1);
    __stcs(((float4*)out) + i, make_float4(f0.x, f0.y, f1.x, f1.y));
}

// ---------------- launch ----------------
extern "C" void kernel_launch(void* const* d_in, const int* in_sizes, int n_in,
                              void* d_out, int out_size) {
    (void)in_sizes; (void)n_in; (void)out_size;
    const int*   ids  = (const int*)d_in[0];
    const float* emb  = (const float*)d_in[1];
    const float* Wih0 = (const float*)d_in[2];
    const float* bih0 = (const float*)d_in[4];
    const float* bhh0 = (const float*)d_in[5];
    const float* Wih1 = (const float*)d_in[6];
    const float* bih1 = (const float*)d_in[8];
    const float* bhh1 = (const float*)d_in[9];
    const float* Wlin = (const float*)d_in[10];
    const float* blin = (const float*)d_in[11];
    float* out = (float*)d_out;

    cudaFuncSetAttribute(fused_gemm,
                         cudaFuncAttributeMaxDynamicSharedMemorySize, L_SMEM);

    f2h_all<<<(589824 + 255) / 256, 256>>>(Wih0, Wih1, Wlin);   // + dedup reset
    mark_k<<<NTOK / 256, 256>>>(ids);
    compact_k<<<(VOCABP + 255) / 256, 256>>>();
    emb_gather<<<(VOCABP * 64) / 256, 256>>>(emb);
    fused_gemm<<<NVT, THREADS, L_SMEM>>>(bih0, bhh0, bih1, bhh1, blin);
    scatter_out<<<(NTOK * 128) / 256, 256>>>(ids, out);
}